// round 9
// baseline (speedup 1.0000x reference)
#include <cuda_runtime.h>
#include <cuda_fp16.h>
#include <cstdint>

// ---------------------------------------------------------------------------
// KQEnergyBlock: B=8, N=1024, D=768, H=12, Z=64, HID=3072
//   Q = x @ Wq^T ; K = x @ Wk^T
//   FA1: per q-block, stream keys: S=Q K^T, Pu=exp(beta S), AV1 = Zinv*(Pu K),
//        Zinv computed inline.  (no attn materialization)
//   FA2: per key-block, stream q: S^T, Pu^T, AV2 = Pu^T (Zinv Q)
//   out = AV1@Wq + AV2@Wk + relu(x@Wmlp^T)@Wmlp       (fp16 mma GEMMs)
// ---------------------------------------------------------------------------

namespace {
constexpr int Bc = 8, Nc = 1024, Dc = 768, Hc = 12, Zc = 64, HIDc = 3072;
constexpr int Mrows = Bc * Nc;  // 8192
}

__device__ __align__(16) __half g_Qh[Mrows * Dc];
__device__ __align__(16) __half g_Kh[Mrows * Dc];
__device__ __align__(16) __half g_KTh[(size_t)Bc * Hc * Zc * Nc];
__device__ __align__(16) __half g_QsTh[(size_t)Bc * Hc * Zc * Nc];
__device__ __align__(16) __half g_AV1h[Mrows * Dc];
__device__ __align__(16) __half g_AV2h[Mrows * Dc];
__device__ __align__(16) __half g_hidh[(size_t)Mrows * HIDc];
__device__ __align__(16) float  g_Zinv[(size_t)Bc * Hc * Nc];
__device__ __align__(16) __half g_xh[Mrows * Dc];
__device__ __align__(16) __half g_Wqh[Dc * Dc];
__device__ __align__(16) __half g_Wkh[Dc * Dc];
__device__ __align__(16) __half g_Wmlph[HIDc * Dc];
__device__ __align__(16) __half g_WqTh[Dc * Dc];
__device__ __align__(16) __half g_WkTh[Dc * Dc];
__device__ __align__(16) __half g_WmlpTh[Dc * HIDc];

enum { E_STOREF = 0, E_ADDF = 1, E_STOREH = 2, E_RELUH = 3 };

__device__ __forceinline__ void cp_async16(void* smem_dst, const void* gmem_src) {
    uint32_t sa = (uint32_t)__cvta_generic_to_shared(smem_dst);
    asm volatile("cp.async.cg.shared.global [%0], [%1], 16;\n" :: "r"(sa), "l"(gmem_src));
}
__device__ __forceinline__ void cp_commit() {
    asm volatile("cp.async.commit_group;\n");
}
template <int Nw>
__device__ __forceinline__ void cp_wait() {
    asm volatile("cp.async.wait_group %0;\n" :: "n"(Nw));
}

__device__ __forceinline__ void mma_f16(float c[4],
                                        uint32_t a0, uint32_t a1, uint32_t a2, uint32_t a3,
                                        uint32_t b0, uint32_t b1) {
    asm volatile(
        "mma.sync.aligned.m16n8k16.row.col.f32.f16.f16.f32 "
        "{%0,%1,%2,%3}, {%4,%5,%6,%7}, {%8,%9}, {%0,%1,%2,%3};\n"
        : "+f"(c[0]), "+f"(c[1]), "+f"(c[2]), "+f"(c[3])
        : "r"(a0), "r"(a1), "r"(a2), "r"(a3), "r"(b0), "r"(b1));
}

// ===========================================================================
// Fused flash attention kernel (template for FA1 / FA2).
//   R block (output rows, 128) resident; iterate 8 C tiles (128):
//     S = R @ C^T (contraction z=64); P = exp(beta*S);
//     AV += P @ T2^T (T2 = [z][ctile], contraction over ctile cols)
//   DO_ZINV: accumulate rowsums, compute Zinv, scale AV rows, write Zinv.
// 4 warps (2x2): S warp tile 64x64, AV warp tile 64x32.
// ===========================================================================
template <int DO_ZINV>
__global__ __launch_bounds__(128, 1)
void fa_k(const __half* __restrict__ Rbase, const __half* __restrict__ Cbase,
          const __half* __restrict__ T2base, __half* __restrict__ Outbase,
          float* __restrict__ zinvg, const float* __restrict__ betas)
{
    extern __shared__ __align__(16) char smem[];
    // [2][128][32] R tile (z-chunked, 64B rows)
    __half (*Rt)[128][32]     = reinterpret_cast<__half(*)[128][32]>(smem);
    // [2 buf][2 zc][128][32] C tile
    __half (*Ct)[2][128][32]  = reinterpret_cast<__half(*)[2][128][32]>(smem + 16384);
    // [2 buf][4 kc][64][32] T2 tile
    __half (*T2)[4][64][32]   = reinterpret_cast<__half(*)[4][64][32]>(smem + 49152);
    // [4 kc][128][32] P tile
    __half (*P)[128][32]      = reinterpret_cast<__half(*)[128][32]>(smem + 81920);
    float (*red)[128]         = reinterpret_cast<float(*)[128]>(smem + 114688);
    float* zs                 = reinterpret_cast<float*>(smem + 115712);

    const int bh = blockIdx.y;
    const int b = bh / Hc, hi = bh % Hc;
    const int blk = blockIdx.x;
    const float beta = betas[hi];

    const __half* Rb = Rbase + ((long)b * Nc + blk * 128) * Dc + hi * Zc;
    const __half* Cb = Cbase + (long)b * Nc * Dc + hi * Zc;
    const __half* T2b = T2base + (long)bh * Zc * Nc;
    __half* Outb = Outbase + ((long)b * Nc + blk * 128) * Dc + hi * Zc;

    const int tid = threadIdx.x;
    const int warp = tid >> 5;
    const int lane = tid & 31;
    const int group = lane >> 2;
    const int tg = lane & 3;
    const int wq = warp >> 1;   // 0..1  (output row half)
    const int wk = warp & 1;    // 0..1  (key half / z half)

    auto loadC = [&](int it2, int s) {
#pragma unroll
        for (int i = 0; i < 8; i++) {
            int c = tid + i * 128;
            int m = c >> 3, r = c & 7;
            int zc = r >> 2, q = r & 3;
            cp_async16(&Ct[s][zc][m][q * 8],
                       &Cb[(long)(it2 * 128 + m) * Dc + zc * 32 + q * 8]);
        }
#pragma unroll
        for (int i = 0; i < 8; i++) {
            int c = tid + i * 128;
            int kc = c >> 8, rem = c & 255;
            int z = rem >> 2, q = rem & 3;
            cp_async16(&T2[s][kc][z][q * 8],
                       &T2b[(long)z * Nc + it2 * 128 + kc * 32 + q * 8]);
        }
        cp_commit();
    };

    // prefetch iter0 tiles + R block (one group)
    {
#pragma unroll
        for (int i = 0; i < 8; i++) {
            int c = tid + i * 128;
            int m = c >> 3, r = c & 7;
            int zc = r >> 2, q = r & 3;
            cp_async16(&Rt[zc][m][q * 8], &Rb[(long)m * Dc + zc * 32 + q * 8]);
        }
        loadC(0, 0);
    }

    float av[4][4][4];
#pragma unroll
    for (int i = 0; i < 4; i++)
#pragma unroll
        for (int j = 0; j < 4; j++)
#pragma unroll
            for (int r = 0; r < 4; r++) av[i][j][r] = 0.f;
    float rs[4][2];
    if (DO_ZINV) {
#pragma unroll
        for (int i = 0; i < 4; i++) { rs[i][0] = 0.f; rs[i][1] = 0.f; }
    }

    for (int it = 0; it < 8; it++) {
        const int s = it & 1;
        if (it + 1 < 8) { loadC(it + 1, s ^ 1); cp_wait<1>(); }
        else            { cp_wait<0>(); }
        __syncthreads();

        // ---- S = R @ C^T  (warp tile 64x64) ----
        float sacc[4][8][4];
#pragma unroll
        for (int i = 0; i < 4; i++)
#pragma unroll
            for (int j = 0; j < 8; j++)
#pragma unroll
                for (int r = 0; r < 4; r++) sacc[i][j][r] = 0.f;

#pragma unroll
        for (int zc = 0; zc < 2; zc++) {
            uint4 a[4][2];
#pragma unroll
            for (int mt = 0; mt < 4; mt++) {
                int mr = wq * 64 + mt * 16 + group;
                a[mt][0] = *reinterpret_cast<const uint4*>(&Rt[zc][mr][tg * 8]);
                a[mt][1] = *reinterpret_cast<const uint4*>(&Rt[zc][mr + 8][tg * 8]);
            }
#pragma unroll
            for (int nt = 0; nt < 8; nt++) {
                int nc = wk * 64 + nt * 8 + group;
                uint4 bb = *reinterpret_cast<const uint4*>(&Ct[s][zc][nc][tg * 8]);
#pragma unroll
                for (int mt = 0; mt < 4; mt++) {
                    mma_f16(sacc[mt][nt], a[mt][0].x, a[mt][1].x, a[mt][0].y, a[mt][1].y,
                            bb.x, bb.y);
                    mma_f16(sacc[mt][nt], a[mt][0].z, a[mt][1].z, a[mt][0].w, a[mt][1].w,
                            bb.z, bb.w);
                }
            }
        }

        // ---- P = exp(beta*S) -> smem (chunked); rowsum ----
#pragma unroll
        for (int mt = 0; mt < 4; mt++) {
            int r0 = wq * 64 + mt * 16 + group;
#pragma unroll
            for (int nt = 0; nt < 8; nt++) {
                float v0 = __expf(beta * sacc[mt][nt][0]);
                float v1 = __expf(beta * sacc[mt][nt][1]);
                float v2 = __expf(beta * sacc[mt][nt][2]);
                float v3 = __expf(beta * sacc[mt][nt][3]);
                if (DO_ZINV) { rs[mt][0] += v0 + v1; rs[mt][1] += v2 + v3; }
                int chunk = wk * 2 + (nt >> 2);
                int colw = (nt & 3) * 8 + tg * 2;
                *reinterpret_cast<__half2*>(&P[chunk][r0][colw]) =
                    __floats2half2_rn(v0, v1);
                *reinterpret_cast<__half2*>(&P[chunk][r0 + 8][colw]) =
                    __floats2half2_rn(v2, v3);
            }
        }
        __syncthreads();

        // ---- AV += P @ T2^T  (warp tile 64 rows x 32 z) ----
#pragma unroll
        for (int kc = 0; kc < 4; kc++) {
            uint4 a[4][2];
#pragma unroll
            for (int mt = 0; mt < 4; mt++) {
                int mr = wq * 64 + mt * 16 + group;
                a[mt][0] = *reinterpret_cast<const uint4*>(&P[kc][mr][tg * 8]);
                a[mt][1] = *reinterpret_cast<const uint4*>(&P[kc][mr + 8][tg * 8]);
            }
#pragma unroll
            for (int nt = 0; nt < 4; nt++) {
                int nc = wk * 32 + nt * 8 + group;
                uint4 bb = *reinterpret_cast<const uint4*>(&T2[s][kc][nc][tg * 8]);
#pragma unroll
                for (int mt = 0; mt < 4; mt++) {
                    mma_f16(av[mt][nt], a[mt][0].x, a[mt][1].x, a[mt][0].y, a[mt][1].y,
                            bb.x, bb.y);
                    mma_f16(av[mt][nt], a[mt][0].z, a[mt][1].z, a[mt][0].w, a[mt][1].w,
                            bb.z, bb.w);
                }
            }
        }
        __syncthreads();
    }

    // ---- Zinv (FA1 only) ----
    if (DO_ZINV) {
#pragma unroll
        for (int mt = 0; mt < 4; mt++) {
#pragma unroll
            for (int h = 0; h < 2; h++) {
                float v = rs[mt][h];
                v += __shfl_xor_sync(0xffffffffu, v, 1);
                v += __shfl_xor_sync(0xffffffffu, v, 2);
                if (tg == 0)
                    red[wk][wq * 64 + mt * 16 + h * 8 + group] = v;
            }
        }
        __syncthreads();
        {
            float ssum = red[0][tid] + red[1][tid];
            float zi = 1.f / ssum;
            zs[tid] = zi;
            zinvg[(long)bh * Nc + blk * 128 + tid] = zi;
        }
        __syncthreads();
    }

    // ---- store AV ----
#pragma unroll
    for (int mt = 0; mt < 4; mt++) {
#pragma unroll
        for (int nt = 0; nt < 4; nt++) {
            int col = wk * 32 + nt * 8 + tg * 2;
#pragma unroll
            for (int h = 0; h < 2; h++) {
                int row = wq * 64 + mt * 16 + h * 8 + group;
                float v0 = av[mt][nt][h * 2 + 0];
                float v1 = av[mt][nt][h * 2 + 1];
                if (DO_ZINV) {
                    float zi = zs[row];
                    v0 *= zi; v1 *= zi;
                }
                *reinterpret_cast<__half2*>(&Outb[(long)row * Dc + col]) =
                    __floats2half2_rn(v0, v1);
            }
        }
    }
}

// ===========================================================================
// Dense half GEMM (unchanged from R8): C = A[m][k] @ B[n][k]^T
// ===========================================================================
template <int BM, int BN, int WM, int WN, int EPI>
__global__ __launch_bounds__((BM / WM) * (BN / WN) * 32)
void gemm_h(const __half* __restrict__ A, const __half* __restrict__ Bm,
            void* __restrict__ Cbase, int K, int lda, int ldb, int ldc)
{
    constexpr int BK = 32;
    constexpr int NW = (BM / WM) * (BN / WN);
    constexpr int NT = NW * 32;
    constexpr int MT = WM / 16;
    constexpr int NTI = WN / 8;
    constexpr int NST = 3;

    __shared__ __align__(16) __half As[NST][BM][BK];
    __shared__ __align__(16) __half Bs[NST][BN][BK];

    const int t = threadIdx.x;
    const int warp = t >> 5;
    const int lane = t & 31;
    const int group = lane >> 2;
    const int tg = lane & 3;
    const int wm = warp / (BN / WN);
    const int wn = warp % (BN / WN);
    const int m0 = blockIdx.y * BM;
    const int n0 = blockIdx.x * BN;

    const int nk = K / BK;

    auto prefetch = [&](int kt, int s) {
        const int k0 = kt * BK;
#pragma unroll
        for (int it = 0; it < (BM * 4) / NT; ++it) {
            int c = t + it * NT;
            int m = c >> 2, q = c & 3;
            cp_async16(&As[s][m][q * 8], &A[(long)(m0 + m) * lda + k0 + q * 8]);
        }
#pragma unroll
        for (int it = 0; it < (BN * 4) / NT; ++it) {
            int c = t + it * NT;
            int n = c >> 2, q = c & 3;
            cp_async16(&Bs[s][n][q * 8], &Bm[(long)(n0 + n) * ldb + k0 + q * 8]);
        }
        cp_commit();
    };

    float acc[MT][NTI][4];
#pragma unroll
    for (int i = 0; i < MT; i++)
#pragma unroll
        for (int j = 0; j < NTI; j++)
#pragma unroll
            for (int r = 0; r < 4; r++) acc[i][j][r] = 0.f;

    prefetch(0, 0);
    if (nk > 1) prefetch(1, 1); else cp_commit();

    for (int kt = 0; kt < nk; kt++) {
        const int s = kt % NST;
        if (kt + 2 < nk) prefetch(kt + 2, (kt + 2) % NST);
        else cp_commit();
        cp_wait<2>();
        __syncthreads();

        uint4 a4[MT][2];
        uint4 b4[NTI];
#pragma unroll
        for (int mt = 0; mt < MT; mt++) {
            int mr = wm * WM + mt * 16 + group;
            a4[mt][0] = *reinterpret_cast<const uint4*>(&As[s][mr][tg * 8]);
            a4[mt][1] = *reinterpret_cast<const uint4*>(&As[s][mr + 8][tg * 8]);
        }
#pragma unroll
        for (int nt = 0; nt < NTI; nt++) {
            int nc = wn * WN + nt * 8 + group;
            b4[nt] = *reinterpret_cast<const uint4*>(&Bs[s][nc][tg * 8]);
        }
#pragma unroll
        for (int mt = 0; mt < MT; mt++)
#pragma unroll
            for (int nt = 0; nt < NTI; nt++)
                mma_f16(acc[mt][nt], a4[mt][0].x, a4[mt][1].x, a4[mt][0].y, a4[mt][1].y,
                        b4[nt].x, b4[nt].y);
#pragma unroll
        for (int mt = 0; mt < MT; mt++)
#pragma unroll
            for (int nt = 0; nt < NTI; nt++)
                mma_f16(acc[mt][nt], a4[mt][0].z, a4[mt][1].z, a4[mt][0].w, a4[mt][1].w,
                        b4[nt].z, b4[nt].w);
        __syncthreads();
    }

#pragma unroll
    for (int mt = 0; mt < MT; mt++) {
#pragma unroll
        for (int nt = 0; nt < NTI; nt++) {
            int gm = m0 + wm * WM + mt * 16 + group;
            int gn = n0 + wn * WN + nt * 8 + tg * 2;
#pragma unroll
            for (int half = 0; half < 2; half++) {
                int row = gm + half * 8;
                float v0 = acc[mt][nt][half * 2 + 0];
                float v1 = acc[mt][nt][half * 2 + 1];
                if (EPI == E_RELUH) { v0 = fmaxf(v0, 0.f); v1 = fmaxf(v1, 0.f); }
                if (EPI == E_STOREF || EPI == E_ADDF) {
                    float* C = (float*)Cbase;
                    float2* p = reinterpret_cast<float2*>(&C[(long)row * ldc + gn]);
                    if (EPI == E_ADDF) {
                        float2 o = *p;
                        p->x = o.x + v0; p->y = o.y + v1;
                    } else {
                        float2 w; w.x = v0; w.y = v1; *p = w;
                    }
                } else {
                    __half* C = (__half*)Cbase;
                    *reinterpret_cast<__half2*>(&C[(long)row * ldc + gn]) =
                        __floats2half2_rn(v0, v1);
                }
            }
        }
    }
}

// ===========================================================================
// Pre-pass kernels
// ===========================================================================
__global__ __launch_bounds__(256) void hconv_k(const float* __restrict__ src,
                                               __half* __restrict__ dst, long n4)
{
    long i = (long)blockIdx.x * 256 + threadIdx.x;
    if (i >= n4) return;
    float4 v = reinterpret_cast<const float4*>(src)[i];
    __half2 h0 = __floats2half2_rn(v.x, v.y);
    __half2 h1 = __floats2half2_rn(v.z, v.w);
    uint2 u;
    u.x = *reinterpret_cast<uint32_t*>(&h0);
    u.y = *reinterpret_cast<uint32_t*>(&h1);
    reinterpret_cast<uint2*>(dst)[i] = u;
}

__global__ __launch_bounds__(256) void htrans_k(const float* __restrict__ src,
                                                __half* __restrict__ dst, int R, int C)
{
    __shared__ float tile[32][33];
    int c0 = blockIdx.x * 32, r0 = blockIdx.y * 32;
    int tx = threadIdx.x & 31, ty = threadIdx.x >> 5;
    for (int i = ty; i < 32; i += 8)
        tile[i][tx] = src[(long)(r0 + i) * C + c0 + tx];
    __syncthreads();
    for (int i = ty; i < 32; i += 8)
        dst[(long)(c0 + i) * R + r0 + tx] = __float2half(tile[tx][i]);
}

// KTh[bh][z][s] = Kh[b, s, h*64+z]
__global__ __launch_bounds__(256) void ktrans_h(const __half* __restrict__ K,
                                                __half* __restrict__ KT)
{
    __shared__ __half tile[32][33];
    int s0 = blockIdx.x * 32, z0 = blockIdx.y * 32, bh = blockIdx.z;
    int b = bh / Hc, h = bh % Hc;
    int tx = threadIdx.x & 31, ty = threadIdx.x >> 5;
    const __half* src = K + (long)b * Nc * Dc + h * Zc;
    for (int i = ty; i < 32; i += 8)
        tile[i][tx] = src[(long)(s0 + i) * Dc + z0 + tx];
    __syncthreads();
    __half* dst = KT + (long)bh * Zc * Nc;
    for (int i = ty; i < 32; i += 8)
        dst[(long)(z0 + i) * Nc + s0 + tx] = tile[tx][i];
}

// QsTh[bh][z][q] = Qh[b, q, h*64+z] * Zinv[bh][q]
__global__ __launch_bounds__(256) void qstrans_h(const __half* __restrict__ Q,
                                                 const float* __restrict__ zinv,
                                                 __half* __restrict__ QT)
{
    __shared__ __half tile[32][33];
    int s0 = blockIdx.x * 32, z0 = blockIdx.y * 32, bh = blockIdx.z;
    int b = bh / Hc, h = bh % Hc;
    int tx = threadIdx.x & 31, ty = threadIdx.x >> 5;
    const __half* src = Q + (long)b * Nc * Dc + h * Zc;
    const float* zv = zinv + (long)bh * Nc;
    for (int i = ty; i < 32; i += 8) {
        float v = __half2float(src[(long)(s0 + i) * Dc + z0 + tx]) * zv[s0 + i];
        tile[i][tx] = __float2half(v);
    }
    __syncthreads();
    __half* dst = QT + (long)bh * Zc * Nc;
    for (int i = ty; i < 32; i += 8)
        dst[(long)(z0 + i) * Nc + s0 + tx] = tile[tx][i];
}

// ===========================================================================
template <int BM, int BN, int WM, int WN, int EPI>
static void run_h(const __half* A, const __half* B, void* C,
                  int M, int N, int K, int lda, int ldb, int ldc)
{
    dim3 grid(N / BN, M / BM);
    gemm_h<BM, BN, WM, WN, EPI>
        <<<grid, (BM / WM) * (BN / WN) * 32>>>(A, B, C, K, lda, ldb, ldc);
}

extern "C" void kernel_launch(void* const* d_in, const int* in_sizes, int n_in,
                              void* d_out, int out_size)
{
    const float* x     = (const float*)d_in[0];
    const float* Wq    = (const float*)d_in[1];
    const float* Wk    = (const float*)d_in[2];
    const float* betas = (const float*)d_in[3];
    const float* Wmlp  = (const float*)d_in[4];
    float* out = (float*)d_out;

    __half *Qh, *Kh, *KTh, *QsTh, *AV1h, *AV2h, *hidh;
    __half *xh, *Wqh, *Wkh, *Wmlph, *WqTh, *WkTh, *WmlpTh;
    float *Zinv;
    cudaGetSymbolAddress((void**)&Qh,     g_Qh);
    cudaGetSymbolAddress((void**)&Kh,     g_Kh);
    cudaGetSymbolAddress((void**)&KTh,    g_KTh);
    cudaGetSymbolAddress((void**)&QsTh,   g_QsTh);
    cudaGetSymbolAddress((void**)&AV1h,   g_AV1h);
    cudaGetSymbolAddress((void**)&AV2h,   g_AV2h);
    cudaGetSymbolAddress((void**)&hidh,   g_hidh);
    cudaGetSymbolAddress((void**)&Zinv,   g_Zinv);
    cudaGetSymbolAddress((void**)&xh,     g_xh);
    cudaGetSymbolAddress((void**)&Wqh,    g_Wqh);
    cudaGetSymbolAddress((void**)&Wkh,    g_Wkh);
    cudaGetSymbolAddress((void**)&Wmlph,  g_Wmlph);
    cudaGetSymbolAddress((void**)&WqTh,   g_WqTh);
    cudaGetSymbolAddress((void**)&WkTh,   g_WkTh);
    cudaGetSymbolAddress((void**)&WmlpTh, g_WmlpTh);

    constexpr int FA_SMEM = 116224;
    cudaFuncSetAttribute(fa_k<1>, cudaFuncAttributeMaxDynamicSharedMemorySize, FA_SMEM);
    cudaFuncSetAttribute(fa_k<0>, cudaFuncAttributeMaxDynamicSharedMemorySize, FA_SMEM);

    // ---- convert inputs to half; build transposed weights ----
    hconv_k<<<(Mrows * Dc / 4 + 255) / 256, 256>>>(x, xh, Mrows * Dc / 4);
    hconv_k<<<(Dc * Dc / 4 + 255) / 256, 256>>>(Wq, Wqh, Dc * Dc / 4);
    hconv_k<<<(Dc * Dc / 4 + 255) / 256, 256>>>(Wk, Wkh, Dc * Dc / 4);
    hconv_k<<<(HIDc * Dc / 4 + 255) / 256, 256>>>(Wmlp, Wmlph, HIDc * Dc / 4);
    htrans_k<<<dim3(Dc / 32, Dc / 32), 256>>>(Wq, WqTh, Dc, Dc);
    htrans_k<<<dim3(Dc / 32, Dc / 32), 256>>>(Wk, WkTh, Dc, Dc);
    htrans_k<<<dim3(Dc / 32, HIDc / 32), 256>>>(Wmlp, WmlpTh, HIDc, Dc);

    // 1) Q = x @ Wq^T ; K = x @ Wk^T
    run_h<128, 128, 64, 64, E_STOREH>(xh, Wqh, Qh, Mrows, Dc, Dc, Dc, Dc, Dc);
    run_h<128, 128, 64, 64, E_STOREH>(xh, Wkh, Kh, Mrows, Dc, Dc, Dc, Dc, Dc);

    ktrans_h<<<dim3(Nc / 32, Zc / 32, Bc * Hc), 256>>>(Kh, KTh);

    // 2) FA1: AV1 + Zinv (R=Q, C=K, T2=KT)
    fa_k<1><<<dim3(Nc / 128, Bc * Hc), 128, FA_SMEM>>>(Qh, Kh, KTh, AV1h, Zinv, betas);

    // 3) Qs = diag(Zinv) Q transposed; FA2: AV2 (R=K, C=Q, T2=QsT)
    qstrans_h<<<dim3(Nc / 32, Zc / 32, Bc * Hc), 256>>>(Qh, Zinv, QsTh);
    fa_k<0><<<dim3(Nc / 128, Bc * Hc), 128, FA_SMEM>>>(Kh, Qh, QsTh, AV2h, Zinv, betas);

    // 4) out = AV1 @ Wq ; out += AV2 @ Wk
    run_h<128, 128, 64, 64, E_STOREF>(AV1h, WqTh, out, Mrows, Dc, Dc, Dc, Dc, Dc);
    run_h<128, 128, 64, 64, E_ADDF>(AV2h, WkTh, out, Mrows, Dc, Dc, Dc, Dc, Dc);

    // 5) hid = relu(x @ Wmlp^T) ; out += hid @ WmlpT^T
    run_h<128, 128, 64, 64, E_RELUH>(xh, Wmlph, hidh, Mrows, HIDc, Dc, Dc, Dc, HIDc);
    run_h<128, 128, 64, 64, E_ADDF>(hidh, WmlpTh, out, Mrows, Dc, HIDc, HIDc, HIDc, Dc);
}

// round 10
// speedup vs baseline: 1.1245x; 1.1245x over previous
#include <cuda_runtime.h>
#include <cuda_fp16.h>
#include <cstdint>

// ---------------------------------------------------------------------------
// KQEnergyBlock: B=8, N=1024, D=768, H=12, Z=64, HID=3072
//   Q = x @ Wq^T ; K = x @ Wk^T
//   FA1 (fused, 8 warps): S=Q K^T, Pu=exp(beta S), AV1=Zinv*(Pu K), Zinv inline
//   FA2 (fused): S^T, Pu^T, AV2 = Pu^T (Zinv Q)
//   AV1/AV2 land in one combined [M][1536] buffer ->
//   out = AVcomb @ [Wq;Wk]_T (single K=1536 GEMM) + relu(x@Wmlp^T)@Wmlp
// ---------------------------------------------------------------------------

namespace {
constexpr int Bc = 8, Nc = 1024, Dc = 768, Hc = 12, Zc = 64, HIDc = 3072;
constexpr int Mrows = Bc * Nc;  // 8192
constexpr int D2 = 2 * Dc;      // 1536
}

__device__ __align__(16) __half g_Qh[Mrows * Dc];
__device__ __align__(16) __half g_Kh[Mrows * Dc];
__device__ __align__(16) __half g_KTh[(size_t)Bc * Hc * Zc * Nc];
__device__ __align__(16) __half g_QsTh[(size_t)Bc * Hc * Zc * Nc];
__device__ __align__(16) __half g_AVh[(size_t)Mrows * D2];          // [AV1|AV2]
__device__ __align__(16) __half g_hidh[(size_t)Mrows * HIDc];
__device__ __align__(16) float  g_Zinv[(size_t)Bc * Hc * Nc];
__device__ __align__(16) __half g_xh[Mrows * Dc];
__device__ __align__(16) __half g_Wqh[Dc * Dc];
__device__ __align__(16) __half g_Wkh[Dc * Dc];
__device__ __align__(16) __half g_Wmlph[HIDc * Dc];
__device__ __align__(16) __half g_W2Th[Dc * D2];                    // [d][e|e']
__device__ __align__(16) __half g_WmlpTh[Dc * HIDc];

enum { E_STOREF = 0, E_ADDF = 1, E_STOREH = 2, E_RELUH = 3 };

__device__ __forceinline__ void cp_async16(void* smem_dst, const void* gmem_src) {
    uint32_t sa = (uint32_t)__cvta_generic_to_shared(smem_dst);
    asm volatile("cp.async.cg.shared.global [%0], [%1], 16;\n" :: "r"(sa), "l"(gmem_src));
}
__device__ __forceinline__ void cp_commit() {
    asm volatile("cp.async.commit_group;\n");
}
template <int Nw>
__device__ __forceinline__ void cp_wait() {
    asm volatile("cp.async.wait_group %0;\n" :: "n"(Nw));
}

__device__ __forceinline__ void mma_f16(float c[4],
                                        uint32_t a0, uint32_t a1, uint32_t a2, uint32_t a3,
                                        uint32_t b0, uint32_t b1) {
    asm volatile(
        "mma.sync.aligned.m16n8k16.row.col.f32.f16.f16.f32 "
        "{%0,%1,%2,%3}, {%4,%5,%6,%7}, {%8,%9}, {%0,%1,%2,%3};\n"
        : "+f"(c[0]), "+f"(c[1]), "+f"(c[2]), "+f"(c[3])
        : "r"(a0), "r"(a1), "r"(a2), "r"(a3), "r"(b0), "r"(b1));
}

// ===========================================================================
// Fused flash attention, 256 threads / 8 warps (2 q-halves x 4 key/z-quarters)
// ===========================================================================
template <int DO_ZINV>
__global__ __launch_bounds__(256, 1)
void fa_k(const __half* __restrict__ Rbase, const __half* __restrict__ Cbase,
          const __half* __restrict__ T2base, __half* __restrict__ Outbase,
          int ldo, float* __restrict__ zinvg, const float* __restrict__ betas)
{
    extern __shared__ __align__(16) char smem[];
    __half (*Rt)[128][32]     = reinterpret_cast<__half(*)[128][32]>(smem);           // [2 zc]
    __half (*Ct)[2][128][32]  = reinterpret_cast<__half(*)[2][128][32]>(smem + 16384);// [2 buf][2 zc]
    __half (*T2)[4][64][32]   = reinterpret_cast<__half(*)[4][64][32]>(smem + 49152); // [2 buf][4 kc]
    __half (*P)[128][32]      = reinterpret_cast<__half(*)[128][32]>(smem + 81920);   // [4 kc]
    float (*red)[128]         = reinterpret_cast<float(*)[128]>(smem + 114688);       // [4][128]
    float* zs                 = reinterpret_cast<float*>(smem + 116736);              // [128]

    const int bh = blockIdx.y;
    const int b = bh / Hc, hi = bh % Hc;
    const int blk = blockIdx.x;
    const float beta = betas[hi];

    const __half* Rb = Rbase + ((long)b * Nc + blk * 128) * Dc + hi * Zc;
    const __half* Cb = Cbase + (long)b * Nc * Dc + hi * Zc;
    const __half* T2b = T2base + (long)bh * Zc * Nc;
    __half* Outb = Outbase + ((long)b * Nc + blk * 128) * ldo + hi * Zc;

    const int tid = threadIdx.x;
    const int warp = tid >> 5;
    const int lane = tid & 31;
    const int group = lane >> 2;
    const int tg = lane & 3;
    const int wq = warp >> 2;   // 0..1  (q half)
    const int wk = warp & 3;    // 0..3  (key quarter / z quarter)

    auto loadC = [&](int it2, int s) {
#pragma unroll
        for (int i = 0; i < 4; i++) {
            int c = tid + i * 256;
            int m = c >> 3, r = c & 7;
            int zc = r >> 2, q = r & 3;
            cp_async16(&Ct[s][zc][m][q * 8],
                       &Cb[(long)(it2 * 128 + m) * Dc + zc * 32 + q * 8]);
        }
#pragma unroll
        for (int i = 0; i < 4; i++) {
            int c = tid + i * 256;
            int kc = c >> 8, rem = c & 255;
            int z = rem >> 2, q = rem & 3;
            cp_async16(&T2[s][kc][z][q * 8],
                       &T2b[(long)z * Nc + it2 * 128 + kc * 32 + q * 8]);
        }
        cp_commit();
    };

    // prefetch R block + iter0 tiles
    {
#pragma unroll
        for (int i = 0; i < 4; i++) {
            int c = tid + i * 256;
            int m = c >> 3, r = c & 7;
            int zc = r >> 2, q = r & 3;
            cp_async16(&Rt[zc][m][q * 8], &Rb[(long)m * Dc + zc * 32 + q * 8]);
        }
        loadC(0, 0);
    }

    float av[4][2][4];
#pragma unroll
    for (int i = 0; i < 4; i++)
#pragma unroll
        for (int j = 0; j < 2; j++)
#pragma unroll
            for (int r = 0; r < 4; r++) av[i][j][r] = 0.f;
    float rs[4][2];
    if (DO_ZINV) {
#pragma unroll
        for (int i = 0; i < 4; i++) { rs[i][0] = 0.f; rs[i][1] = 0.f; }
    }

    for (int it = 0; it < 8; it++) {
        const int s = it & 1;
        if (it + 1 < 8) { loadC(it + 1, s ^ 1); cp_wait<1>(); }
        else            { cp_wait<0>(); }
        __syncthreads();

        // ---- S = R @ C^T  (warp tile 64q x 32k) ----
        float sacc[4][4][4];
#pragma unroll
        for (int i = 0; i < 4; i++)
#pragma unroll
            for (int j = 0; j < 4; j++)
#pragma unroll
                for (int r = 0; r < 4; r++) sacc[i][j][r] = 0.f;

#pragma unroll
        for (int zc = 0; zc < 2; zc++) {
            uint4 a[4][2];
#pragma unroll
            for (int mt = 0; mt < 4; mt++) {
                int mr = wq * 64 + mt * 16 + group;
                a[mt][0] = *reinterpret_cast<const uint4*>(&Rt[zc][mr][tg * 8]);
                a[mt][1] = *reinterpret_cast<const uint4*>(&Rt[zc][mr + 8][tg * 8]);
            }
#pragma unroll
            for (int nt = 0; nt < 4; nt++) {
                int nc = wk * 32 + nt * 8 + group;
                uint4 bb = *reinterpret_cast<const uint4*>(&Ct[s][zc][nc][tg * 8]);
#pragma unroll
                for (int mt = 0; mt < 4; mt++) {
                    mma_f16(sacc[mt][nt], a[mt][0].x, a[mt][1].x, a[mt][0].y, a[mt][1].y,
                            bb.x, bb.y);
                    mma_f16(sacc[mt][nt], a[mt][0].z, a[mt][1].z, a[mt][0].w, a[mt][1].w,
                            bb.z, bb.w);
                }
            }
        }

        // ---- P = exp(beta*S) -> smem chunk wk; rowsum ----
#pragma unroll
        for (int mt = 0; mt < 4; mt++) {
            int r0 = wq * 64 + mt * 16 + group;
#pragma unroll
            for (int nt = 0; nt < 4; nt++) {
                float v0 = __expf(beta * sacc[mt][nt][0]);
                float v1 = __expf(beta * sacc[mt][nt][1]);
                float v2 = __expf(beta * sacc[mt][nt][2]);
                float v3 = __expf(beta * sacc[mt][nt][3]);
                if (DO_ZINV) { rs[mt][0] += v0 + v1; rs[mt][1] += v2 + v3; }
                int colw = nt * 8 + tg * 2;
                *reinterpret_cast<__half2*>(&P[wk][r0][colw]) =
                    __floats2half2_rn(v0, v1);
                *reinterpret_cast<__half2*>(&P[wk][r0 + 8][colw]) =
                    __floats2half2_rn(v2, v3);
            }
        }
        __syncthreads();

        // ---- AV += P @ T2^T  (warp tile 64q x 16z) ----
#pragma unroll
        for (int kc = 0; kc < 4; kc++) {
            uint4 a[4][2];
#pragma unroll
            for (int mt = 0; mt < 4; mt++) {
                int mr = wq * 64 + mt * 16 + group;
                a[mt][0] = *reinterpret_cast<const uint4*>(&P[kc][mr][tg * 8]);
                a[mt][1] = *reinterpret_cast<const uint4*>(&P[kc][mr + 8][tg * 8]);
            }
#pragma unroll
            for (int nt = 0; nt < 2; nt++) {
                int nc = wk * 16 + nt * 8 + group;
                uint4 bb = *reinterpret_cast<const uint4*>(&T2[s][kc][nc][tg * 8]);
#pragma unroll
                for (int mt = 0; mt < 4; mt++) {
                    mma_f16(av[mt][nt], a[mt][0].x, a[mt][1].x, a[mt][0].y, a[mt][1].y,
                            bb.x, bb.y);
                    mma_f16(av[mt][nt], a[mt][0].z, a[mt][1].z, a[mt][0].w, a[mt][1].w,
                            bb.z, bb.w);
                }
            }
        }
        __syncthreads();
    }

    // ---- Zinv (FA1 only) ----
    if (DO_ZINV) {
#pragma unroll
        for (int mt = 0; mt < 4; mt++) {
#pragma unroll
            for (int h = 0; h < 2; h++) {
                float v = rs[mt][h];
                v += __shfl_xor_sync(0xffffffffu, v, 1);
                v += __shfl_xor_sync(0xffffffffu, v, 2);
                if (tg == 0)
                    red[wk][wq * 64 + mt * 16 + h * 8 + group] = v;
            }
        }
        __syncthreads();
        if (tid < 128) {
            float ssum = red[0][tid] + red[1][tid] + red[2][tid] + red[3][tid];
            float zi = 1.f / ssum;
            zs[tid] = zi;
            zinvg[(long)bh * Nc + blk * 128 + tid] = zi;
        }
        __syncthreads();
    }

    // ---- store AV ----
#pragma unroll
    for (int mt = 0; mt < 4; mt++) {
#pragma unroll
        for (int nt = 0; nt < 2; nt++) {
            int col = wk * 16 + nt * 8 + tg * 2;
#pragma unroll
            for (int h = 0; h < 2; h++) {
                int row = wq * 64 + mt * 16 + h * 8 + group;
                float v0 = av[mt][nt][h * 2 + 0];
                float v1 = av[mt][nt][h * 2 + 1];
                if (DO_ZINV) {
                    float zi = zs[row];
                    v0 *= zi; v1 *= zi;
                }
                *reinterpret_cast<__half2*>(&Outb[(long)row * ldo + col]) =
                    __floats2half2_rn(v0, v1);
            }
        }
    }
}

// ===========================================================================
// Dense half GEMM: C = A[m][k] @ B[n][k]^T  (proven R8 kernel)
// ===========================================================================
template <int BM, int BN, int WM, int WN, int EPI>
__global__ __launch_bounds__((BM / WM) * (BN / WN) * 32)
void gemm_h(const __half* __restrict__ A, const __half* __restrict__ Bm,
            void* __restrict__ Cbase, int K, int lda, int ldb, int ldc)
{
    constexpr int BK = 32;
    constexpr int NW = (BM / WM) * (BN / WN);
    constexpr int NT = NW * 32;
    constexpr int MT = WM / 16;
    constexpr int NTI = WN / 8;
    constexpr int NST = 3;

    __shared__ __align__(16) __half As[NST][BM][BK];
    __shared__ __align__(16) __half Bs[NST][BN][BK];

    const int t = threadIdx.x;
    const int warp = t >> 5;
    const int lane = t & 31;
    const int group = lane >> 2;
    const int tg = lane & 3;
    const int wm = warp / (BN / WN);
    const int wn = warp % (BN / WN);
    const int m0 = blockIdx.y * BM;
    const int n0 = blockIdx.x * BN;

    const int nk = K / BK;

    auto prefetch = [&](int kt, int s) {
        const int k0 = kt * BK;
#pragma unroll
        for (int it = 0; it < (BM * 4) / NT; ++it) {
            int c = t + it * NT;
            int m = c >> 2, q = c & 3;
            cp_async16(&As[s][m][q * 8], &A[(long)(m0 + m) * lda + k0 + q * 8]);
        }
#pragma unroll
        for (int it = 0; it < (BN * 4) / NT; ++it) {
            int c = t + it * NT;
            int n = c >> 2, q = c & 3;
            cp_async16(&Bs[s][n][q * 8], &Bm[(long)(n0 + n) * ldb + k0 + q * 8]);
        }
        cp_commit();
    };

    float acc[MT][NTI][4];
#pragma unroll
    for (int i = 0; i < MT; i++)
#pragma unroll
        for (int j = 0; j < NTI; j++)
#pragma unroll
            for (int r = 0; r < 4; r++) acc[i][j][r] = 0.f;

    prefetch(0, 0);
    if (nk > 1) prefetch(1, 1); else cp_commit();

    for (int kt = 0; kt < nk; kt++) {
        const int s = kt % NST;
        if (kt + 2 < nk) prefetch(kt + 2, (kt + 2) % NST);
        else cp_commit();
        cp_wait<2>();
        __syncthreads();

        uint4 a4[MT][2];
        uint4 b4[NTI];
#pragma unroll
        for (int mt = 0; mt < MT; mt++) {
            int mr = wm * WM + mt * 16 + group;
            a4[mt][0] = *reinterpret_cast<const uint4*>(&As[s][mr][tg * 8]);
            a4[mt][1] = *reinterpret_cast<const uint4*>(&As[s][mr + 8][tg * 8]);
        }
#pragma unroll
        for (int nt = 0; nt < NTI; nt++) {
            int nc = wn * WN + nt * 8 + group;
            b4[nt] = *reinterpret_cast<const uint4*>(&Bs[s][nc][tg * 8]);
        }
#pragma unroll
        for (int mt = 0; mt < MT; mt++)
#pragma unroll
            for (int nt = 0; nt < NTI; nt++)
                mma_f16(acc[mt][nt], a4[mt][0].x, a4[mt][1].x, a4[mt][0].y, a4[mt][1].y,
                        b4[nt].x, b4[nt].y);
#pragma unroll
        for (int mt = 0; mt < MT; mt++)
#pragma unroll
            for (int nt = 0; nt < NTI; nt++)
                mma_f16(acc[mt][nt], a4[mt][0].z, a4[mt][1].z, a4[mt][0].w, a4[mt][1].w,
                        b4[nt].z, b4[nt].w);
        __syncthreads();
    }

#pragma unroll
    for (int mt = 0; mt < MT; mt++) {
#pragma unroll
        for (int nt = 0; nt < NTI; nt++) {
            int gm = m0 + wm * WM + mt * 16 + group;
            int gn = n0 + wn * WN + nt * 8 + tg * 2;
#pragma unroll
            for (int half = 0; half < 2; half++) {
                int row = gm + half * 8;
                float v0 = acc[mt][nt][half * 2 + 0];
                float v1 = acc[mt][nt][half * 2 + 1];
                if (EPI == E_RELUH) { v0 = fmaxf(v0, 0.f); v1 = fmaxf(v1, 0.f); }
                if (EPI == E_STOREF || EPI == E_ADDF) {
                    float* C = (float*)Cbase;
                    float2* p = reinterpret_cast<float2*>(&C[(long)row * ldc + gn]);
                    if (EPI == E_ADDF) {
                        float2 o = *p;
                        p->x = o.x + v0; p->y = o.y + v1;
                    } else {
                        float2 w; w.x = v0; w.y = v1; *p = w;
                    }
                } else {
                    __half* C = (__half*)Cbase;
                    *reinterpret_cast<__half2*>(&C[(long)row * ldc + gn]) =
                        __floats2half2_rn(v0, v1);
                }
            }
        }
    }
}

// ===========================================================================
// Pre-pass kernels
// ===========================================================================
__global__ __launch_bounds__(256) void hconv_k(const float* __restrict__ src,
                                               __half* __restrict__ dst, long n4)
{
    long i = (long)blockIdx.x * 256 + threadIdx.x;
    if (i >= n4) return;
    float4 v = reinterpret_cast<const float4*>(src)[i];
    __half2 h0 = __floats2half2_rn(v.x, v.y);
    __half2 h1 = __floats2half2_rn(v.z, v.w);
    uint2 u;
    u.x = *reinterpret_cast<uint32_t*>(&h0);
    u.y = *reinterpret_cast<uint32_t*>(&h1);
    reinterpret_cast<uint2*>(dst)[i] = u;
}

// dst[c][r] = half(src[r][c]) with dst row stride dld
__global__ __launch_bounds__(256) void htrans_k(const float* __restrict__ src,
                                                __half* __restrict__ dst,
                                                int R, int C, int dld)
{
    __shared__ float tile[32][33];
    int c0 = blockIdx.x * 32, r0 = blockIdx.y * 32;
    int tx = threadIdx.x & 31, ty = threadIdx.x >> 5;
    for (int i = ty; i < 32; i += 8)
        tile[i][tx] = src[(long)(r0 + i) * C + c0 + tx];
    __syncthreads();
    for (int i = ty; i < 32; i += 8)
        dst[(long)(c0 + i) * dld + r0 + tx] = __float2half(tile[tx][i]);
}

// KTh[bh][z][s] = Kh[b, s, h*64+z]
__global__ __launch_bounds__(256) void ktrans_h(const __half* __restrict__ K,
                                                __half* __restrict__ KT)
{
    __shared__ __half tile[32][33];
    int s0 = blockIdx.x * 32, z0 = blockIdx.y * 32, bh = blockIdx.z;
    int b = bh / Hc, h = bh % Hc;
    int tx = threadIdx.x & 31, ty = threadIdx.x >> 5;
    const __half* src = K + (long)b * Nc * Dc + h * Zc;
    for (int i = ty; i < 32; i += 8)
        tile[i][tx] = src[(long)(s0 + i) * Dc + z0 + tx];
    __syncthreads();
    __half* dst = KT + (long)bh * Zc * Nc;
    for (int i = ty; i < 32; i += 8)
        dst[(long)(z0 + i) * Nc + s0 + tx] = tile[tx][i];
}

// QsTh[bh][z][q] = Qh[b, q, h*64+z] * Zinv[bh][q]
__global__ __launch_bounds__(256) void qstrans_h(const __half* __restrict__ Q,
                                                 const float* __restrict__ zinv,
                                                 __half* __restrict__ QT)
{
    __shared__ __half tile[32][33];
    int s0 = blockIdx.x * 32, z0 = blockIdx.y * 32, bh = blockIdx.z;
    int b = bh / Hc, h = bh % Hc;
    int tx = threadIdx.x & 31, ty = threadIdx.x >> 5;
    const __half* src = Q + (long)b * Nc * Dc + h * Zc;
    const float* zv = zinv + (long)bh * Nc;
    for (int i = ty; i < 32; i += 8) {
        float v = __half2float(src[(long)(s0 + i) * Dc + z0 + tx]) * zv[s0 + i];
        tile[i][tx] = __float2half(v);
    }
    __syncthreads();
    __half* dst = QT + (long)bh * Zc * Nc;
    for (int i = ty; i < 32; i += 8)
        dst[(long)(z0 + i) * Nc + s0 + tx] = tile[tx][i];
}

// ===========================================================================
template <int BM, int BN, int WM, int WN, int EPI>
static void run_h(const __half* A, const __half* B, void* C,
                  int M, int N, int K, int lda, int ldb, int ldc)
{
    dim3 grid(N / BN, M / BM);
    gemm_h<BM, BN, WM, WN, EPI>
        <<<grid, (BM / WM) * (BN / WN) * 32>>>(A, B, C, K, lda, ldb, ldc);
}

extern "C" void kernel_launch(void* const* d_in, const int* in_sizes, int n_in,
                              void* d_out, int out_size)
{
    const float* x     = (const float*)d_in[0];
    const float* Wq    = (const float*)d_in[1];
    const float* Wk    = (const float*)d_in[2];
    const float* betas = (const float*)d_in[3];
    const float* Wmlp  = (const float*)d_in[4];
    float* out = (float*)d_out;

    __half *Qh, *Kh, *KTh, *QsTh, *AVh, *hidh;
    __half *xh, *Wqh, *Wkh, *Wmlph, *W2Th, *WmlpTh;
    float *Zinv;
    cudaGetSymbolAddress((void**)&Qh,     g_Qh);
    cudaGetSymbolAddress((void**)&Kh,     g_Kh);
    cudaGetSymbolAddress((void**)&KTh,    g_KTh);
    cudaGetSymbolAddress((void**)&QsTh,   g_QsTh);
    cudaGetSymbolAddress((void**)&AVh,    g_AVh);
    cudaGetSymbolAddress((void**)&hidh,   g_hidh);
    cudaGetSymbolAddress((void**)&Zinv,   g_Zinv);
    cudaGetSymbolAddress((void**)&xh,     g_xh);
    cudaGetSymbolAddress((void**)&Wqh,    g_Wqh);
    cudaGetSymbolAddress((void**)&Wkh,    g_Wkh);
    cudaGetSymbolAddress((void**)&Wmlph,  g_Wmlph);
    cudaGetSymbolAddress((void**)&W2Th,   g_W2Th);
    cudaGetSymbolAddress((void**)&WmlpTh, g_WmlpTh);

    constexpr int FA_SMEM = 117248;
    cudaFuncSetAttribute(fa_k<1>, cudaFuncAttributeMaxDynamicSharedMemorySize, FA_SMEM);
    cudaFuncSetAttribute(fa_k<0>, cudaFuncAttributeMaxDynamicSharedMemorySize, FA_SMEM);

    // ---- convert inputs to half; build transposed weights ----
    hconv_k<<<(Mrows * Dc / 4 + 255) / 256, 256>>>(x, xh, Mrows * Dc / 4);
    hconv_k<<<(Dc * Dc / 4 + 255) / 256, 256>>>(Wq, Wqh, Dc * Dc / 4);
    hconv_k<<<(Dc * Dc / 4 + 255) / 256, 256>>>(Wk, Wkh, Dc * Dc / 4);
    hconv_k<<<(HIDc * Dc / 4 + 255) / 256, 256>>>(Wmlp, Wmlph, HIDc * Dc / 4);
    // W2T[d][0:768] = WqT, W2T[d][768:1536] = WkT
    htrans_k<<<dim3(Dc / 32, Dc / 32), 256>>>(Wq, W2Th, Dc, Dc, D2);
    htrans_k<<<dim3(Dc / 32, Dc / 32), 256>>>(Wk, W2Th + Dc, Dc, Dc, D2);
    htrans_k<<<dim3(Dc / 32, HIDc / 32), 256>>>(Wmlp, WmlpTh, HIDc, Dc, HIDc);

    // 1) Q = x @ Wq^T ; K = x @ Wk^T
    run_h<128, 128, 64, 64, E_STOREH>(xh, Wqh, Qh, Mrows, Dc, Dc, Dc, Dc, Dc);
    run_h<128, 128, 64, 64, E_STOREH>(xh, Wkh, Kh, Mrows, Dc, Dc, Dc, Dc, Dc);

    ktrans_h<<<dim3(Nc / 32, Zc / 32, Bc * Hc), 256>>>(Kh, KTh);

    // 2) FA1: AV1 (cols 0:768 of AVh) + Zinv
    fa_k<1><<<dim3(Nc / 128, Bc * Hc), 256, FA_SMEM>>>(Qh, Kh, KTh, AVh, D2, Zinv, betas);

    // 3) Qs = diag(Zinv) Q transposed; FA2: AV2 (cols 768:1536)
    qstrans_h<<<dim3(Nc / 32, Zc / 32, Bc * Hc), 256>>>(Qh, Zinv, QsTh);
    fa_k<0><<<dim3(Nc / 128, Bc * Hc), 256, FA_SMEM>>>(Kh, Qh, QsTh, AVh + Dc, D2, Zinv, betas);

    // 4) out = [AV1 AV2] @ [Wq;Wk]  (single K=1536 GEMM)
    run_h<128, 128, 64, 64, E_STOREF>(AVh, W2Th, out, Mrows, Dc, D2, D2, D2, Dc);

    // 5) hid = relu(x @ Wmlp^T) ; out += hid @ WmlpT^T
    run_h<128, 128, 64, 64, E_RELUH>(xh, Wmlph, hidh, Mrows, HIDc, Dc, Dc, Dc, HIDc);
    run_h<128, 128, 64, 64, E_ADDF>(hidh, WmlpTh, out, Mrows, Dc, HIDc, HIDc, HIDc, Dc);
}

// round 11
// speedup vs baseline: 1.2045x; 1.0712x over previous
#include <cuda_runtime.h>
#include <cuda_fp16.h>
#include <cstdint>

// ---------------------------------------------------------------------------
// KQEnergyBlock: B=8, N=1024, D=768, H=12, Z=64, HID=3072
//   Q = x @ Wq^T ; K = x @ Wk^T
//   FA1 (fused, 8 warps, exp/mma software-pipelined):
//        S=Q K^T, Pu=exp(beta S), AV1=Zinv*(Pu K), Zinv inline
//   FA2: S^T, Pu^T, AV2 = Pu^T (Zinv Q)
//   hid = relu(x @ Wmlp^T)
//   AV1|AV2|hid land in one combined [M][4608] buffer ->
//   out = comb @ [Wq;Wk;Wmlp]-stacked  (single K=4608 GEMM)
// ---------------------------------------------------------------------------

namespace {
constexpr int Bc = 8, Nc = 1024, Dc = 768, Hc = 12, Zc = 64, HIDc = 3072;
constexpr int Mrows = Bc * Nc;   // 8192
constexpr int KC = 2 * Dc + HIDc; // 4608 combined K
}

__device__ __align__(16) __half g_Qh[Mrows * Dc];
__device__ __align__(16) __half g_Kh[Mrows * Dc];
__device__ __align__(16) __half g_KTh[(size_t)Bc * Hc * Zc * Nc];
__device__ __align__(16) __half g_QsTh[(size_t)Bc * Hc * Zc * Nc];
__device__ __align__(16) __half g_AVh[(size_t)Mrows * KC];   // [AV1|AV2|hid]
__device__ __align__(16) float  g_Zinv[(size_t)Bc * Hc * Nc];
__device__ __align__(16) __half g_xh[Mrows * Dc];
__device__ __align__(16) __half g_Wqh[Dc * Dc];
__device__ __align__(16) __half g_Wkh[Dc * Dc];
__device__ __align__(16) __half g_Wmlph[HIDc * Dc];
__device__ __align__(16) __half g_WallTh[(size_t)Dc * KC];   // [d][e|e'|h]

enum { E_STOREF = 0, E_STOREH = 2, E_RELUH = 3 };

__device__ __forceinline__ void cp_async16(void* smem_dst, const void* gmem_src) {
    uint32_t sa = (uint32_t)__cvta_generic_to_shared(smem_dst);
    asm volatile("cp.async.cg.shared.global [%0], [%1], 16;\n" :: "r"(sa), "l"(gmem_src));
}
__device__ __forceinline__ void cp_commit() {
    asm volatile("cp.async.commit_group;\n");
}
template <int Nw>
__device__ __forceinline__ void cp_wait() {
    asm volatile("cp.async.wait_group %0;\n" :: "n"(Nw));
}

__device__ __forceinline__ void mma_f16(float c[4],
                                        uint32_t a0, uint32_t a1, uint32_t a2, uint32_t a3,
                                        uint32_t b0, uint32_t b1) {
    asm volatile(
        "mma.sync.aligned.m16n8k16.row.col.f32.f16.f16.f32 "
        "{%0,%1,%2,%3}, {%4,%5,%6,%7}, {%8,%9}, {%0,%1,%2,%3};\n"
        : "+f"(c[0]), "+f"(c[1]), "+f"(c[2]), "+f"(c[3])
        : "r"(a0), "r"(a1), "r"(a2), "r"(a3), "r"(b0), "r"(b1));
}

// ===========================================================================
// Fused flash attention, 256 threads / 8 warps, exp overlapped with AV-mma.
// smem: Rt[2]16K | Ct[4][2]64K | T2[4][4]64K | P[2][4]64K | red 2K | zs .5K
// ===========================================================================
namespace fa {
constexpr int OFF_R  = 0;
constexpr int OFF_C  = 16384;
constexpr int OFF_T2 = 81920;
constexpr int OFF_P  = 147456;
constexpr int OFF_RED = 212992;
constexpr int OFF_ZS  = 215040;
constexpr int SMEM    = 215552;
}

template <int DO_ZINV>
__global__ __launch_bounds__(256, 1)
void fa_k(const __half* __restrict__ Rbase, const __half* __restrict__ Cbase,
          const __half* __restrict__ T2base, __half* __restrict__ Outbase,
          int ldo, float* __restrict__ zinvg, const float* __restrict__ betas)
{
    extern __shared__ __align__(16) char smem[];
    __half (*Rt)[128][32]     = reinterpret_cast<__half(*)[128][32]>(smem + fa::OFF_R);
    __half (*Ct)[2][128][32]  = reinterpret_cast<__half(*)[2][128][32]>(smem + fa::OFF_C);
    __half (*T2)[4][64][32]   = reinterpret_cast<__half(*)[4][64][32]>(smem + fa::OFF_T2);
    __half (*P)[4][128][32]   = reinterpret_cast<__half(*)[4][128][32]>(smem + fa::OFF_P);
    float (*red)[128]         = reinterpret_cast<float(*)[128]>(smem + fa::OFF_RED);
    float* zs                 = reinterpret_cast<float*>(smem + fa::OFF_ZS);

    const int bh = blockIdx.y;
    const int b = bh / Hc, hi = bh % Hc;
    const int blk = blockIdx.x;
    const float beta = betas[hi];

    const __half* Rb = Rbase + ((long)b * Nc + blk * 128) * Dc + hi * Zc;
    const __half* Cb = Cbase + (long)b * Nc * Dc + hi * Zc;
    const __half* T2b = T2base + (long)bh * Zc * Nc;
    __half* Outb = Outbase + ((long)b * Nc + blk * 128) * ldo + hi * Zc;

    const int tid = threadIdx.x;
    const int warp = tid >> 5;
    const int lane = tid & 31;
    const int group = lane >> 2;
    const int tg = lane & 3;
    const int wq = warp >> 2;   // 0..1
    const int wk = warp & 3;    // 0..3

    auto loadC = [&](int it2, int s) {
#pragma unroll
        for (int i = 0; i < 4; i++) {
            int c = tid + i * 256;
            int m = c >> 3, r = c & 7;
            int zc = r >> 2, q = r & 3;
            cp_async16(&Ct[s][zc][m][q * 8],
                       &Cb[(long)(it2 * 128 + m) * Dc + zc * 32 + q * 8]);
        }
#pragma unroll
        for (int i = 0; i < 4; i++) {
            int c = tid + i * 256;
            int kc = c >> 8, rem = c & 255;
            int z = rem >> 2, q = rem & 3;
            cp_async16(&T2[s][kc][z][q * 8],
                       &T2b[(long)z * Nc + it2 * 128 + kc * 32 + q * 8]);
        }
        cp_commit();
    };

    {   // prefetch R block + iter0 (same commit group), then iter1
#pragma unroll
        for (int i = 0; i < 4; i++) {
            int c = tid + i * 256;
            int m = c >> 3, r = c & 7;
            int zc = r >> 2, q = r & 3;
            cp_async16(&Rt[zc][m][q * 8], &Rb[(long)m * Dc + zc * 32 + q * 8]);
        }
        loadC(0, 0);
        loadC(1, 1);
    }

    float av[4][2][4];
#pragma unroll
    for (int i = 0; i < 4; i++)
#pragma unroll
        for (int j = 0; j < 2; j++)
#pragma unroll
            for (int r = 0; r < 4; r++) av[i][j][r] = 0.f;
    float rs[4][2];
    if (DO_ZINV) {
#pragma unroll
        for (int i = 0; i < 4; i++) { rs[i][0] = 0.f; rs[i][1] = 0.f; }
    }

    for (int it = 0; it < 8; it++) {
        const int s = it & 3;
        if (it + 2 < 8) loadC(it + 2, (it + 2) & 3);
        else cp_commit();
        cp_wait<2>();
        __syncthreads();

        // ---- S(it) = R @ C^T  (warp tile 64q x 32k) ----
        float sacc[4][4][4];
#pragma unroll
        for (int i = 0; i < 4; i++)
#pragma unroll
            for (int j = 0; j < 4; j++)
#pragma unroll
                for (int r = 0; r < 4; r++) sacc[i][j][r] = 0.f;

#pragma unroll
        for (int zc = 0; zc < 2; zc++) {
            uint4 a[4][2];
#pragma unroll
            for (int mt = 0; mt < 4; mt++) {
                int mr = wq * 64 + mt * 16 + group;
                a[mt][0] = *reinterpret_cast<const uint4*>(&Rt[zc][mr][tg * 8]);
                a[mt][1] = *reinterpret_cast<const uint4*>(&Rt[zc][mr + 8][tg * 8]);
            }
#pragma unroll
            for (int nt = 0; nt < 4; nt++) {
                int nc = wk * 32 + nt * 8 + group;
                uint4 bb = *reinterpret_cast<const uint4*>(&Ct[s][zc][nc][tg * 8]);
#pragma unroll
                for (int mt = 0; mt < 4; mt++) {
                    mma_f16(sacc[mt][nt], a[mt][0].x, a[mt][1].x, a[mt][0].y, a[mt][1].y,
                            bb.x, bb.y);
                    mma_f16(sacc[mt][nt], a[mt][0].z, a[mt][1].z, a[mt][0].w, a[mt][1].w,
                            bb.z, bb.w);
                }
            }
        }

        // ---- interleave: AV(it-1) mma  +  exp(it) -> P[pcur] ----
        const int pcur = it & 1;
        const int pprev = pcur ^ 1;
        const int sprev = (it + 3) & 3;   // (it-1) mod 4

#pragma unroll
        for (int j = 0; j < 4; j++) {
            if (it > 0) {
                uint4 a[4][2];
#pragma unroll
                for (int mt = 0; mt < 4; mt++) {
                    int mr = wq * 64 + mt * 16 + group;
                    a[mt][0] = *reinterpret_cast<const uint4*>(&P[pprev][j][mr][tg * 8]);
                    a[mt][1] = *reinterpret_cast<const uint4*>(&P[pprev][j][mr + 8][tg * 8]);
                }
#pragma unroll
                for (int nt = 0; nt < 2; nt++) {
                    int nc = wk * 16 + nt * 8 + group;
                    uint4 bb = *reinterpret_cast<const uint4*>(&T2[sprev][j][nc][tg * 8]);
#pragma unroll
                    for (int mt = 0; mt < 4; mt++) {
                        mma_f16(av[mt][nt], a[mt][0].x, a[mt][1].x, a[mt][0].y, a[mt][1].y,
                                bb.x, bb.y);
                        mma_f16(av[mt][nt], a[mt][0].z, a[mt][1].z, a[mt][0].w, a[mt][1].w,
                                bb.z, bb.w);
                    }
                }
            }
            // exp chunk nt=j of sacc (writes this warp's key-quarter wk)
#pragma unroll
            for (int mt = 0; mt < 4; mt++) {
                int r0 = wq * 64 + mt * 16 + group;
                float v0 = __expf(beta * sacc[mt][j][0]);
                float v1 = __expf(beta * sacc[mt][j][1]);
                float v2 = __expf(beta * sacc[mt][j][2]);
                float v3 = __expf(beta * sacc[mt][j][3]);
                if (DO_ZINV) { rs[mt][0] += v0 + v1; rs[mt][1] += v2 + v3; }
                int colw = j * 8 + tg * 2;
                *reinterpret_cast<__half2*>(&P[pcur][wk][r0][colw]) =
                    __floats2half2_rn(v0, v1);
                *reinterpret_cast<__half2*>(&P[pcur][wk][r0 + 8][colw]) =
                    __floats2half2_rn(v2, v3);
            }
        }
        __syncthreads();
    }

    // ---- epilogue: AV(7) (P buf 1, T2 stage 3) ----
#pragma unroll
    for (int j = 0; j < 4; j++) {
        uint4 a[4][2];
#pragma unroll
        for (int mt = 0; mt < 4; mt++) {
            int mr = wq * 64 + mt * 16 + group;
            a[mt][0] = *reinterpret_cast<const uint4*>(&P[1][j][mr][tg * 8]);
            a[mt][1] = *reinterpret_cast<const uint4*>(&P[1][j][mr + 8][tg * 8]);
        }
#pragma unroll
        for (int nt = 0; nt < 2; nt++) {
            int nc = wk * 16 + nt * 8 + group;
            uint4 bb = *reinterpret_cast<const uint4*>(&T2[3][j][nc][tg * 8]);
#pragma unroll
            for (int mt = 0; mt < 4; mt++) {
                mma_f16(av[mt][nt], a[mt][0].x, a[mt][1].x, a[mt][0].y, a[mt][1].y,
                        bb.x, bb.y);
                mma_f16(av[mt][nt], a[mt][0].z, a[mt][1].z, a[mt][0].w, a[mt][1].w,
                        bb.z, bb.w);
            }
        }
    }

    // ---- Zinv (FA1 only) ----
    if (DO_ZINV) {
#pragma unroll
        for (int mt = 0; mt < 4; mt++) {
#pragma unroll
            for (int h = 0; h < 2; h++) {
                float v = rs[mt][h];
                v += __shfl_xor_sync(0xffffffffu, v, 1);
                v += __shfl_xor_sync(0xffffffffu, v, 2);
                if (tg == 0)
                    red[wk][wq * 64 + mt * 16 + h * 8 + group] = v;
            }
        }
        __syncthreads();
        if (tid < 128) {
            float ssum = red[0][tid] + red[1][tid] + red[2][tid] + red[3][tid];
            float zi = 1.f / ssum;
            zs[tid] = zi;
            zinvg[(long)bh * Nc + blk * 128 + tid] = zi;
        }
        __syncthreads();
    }

    // ---- store AV ----
#pragma unroll
    for (int mt = 0; mt < 4; mt++) {
#pragma unroll
        for (int nt = 0; nt < 2; nt++) {
            int col = wk * 16 + nt * 8 + tg * 2;
#pragma unroll
            for (int h = 0; h < 2; h++) {
                int row = wq * 64 + mt * 16 + h * 8 + group;
                float v0 = av[mt][nt][h * 2 + 0];
                float v1 = av[mt][nt][h * 2 + 1];
                if (DO_ZINV) {
                    float zi = zs[row];
                    v0 *= zi; v1 *= zi;
                }
                *reinterpret_cast<__half2*>(&Outb[(long)row * ldo + col]) =
                    __floats2half2_rn(v0, v1);
            }
        }
    }
}

// ===========================================================================
// Dense half GEMM: C = A[m][k] @ B[n][k]^T  (proven R8/R10 kernel)
// ===========================================================================
template <int BM, int BN, int WM, int WN, int EPI>
__global__ __launch_bounds__((BM / WM) * (BN / WN) * 32)
void gemm_h(const __half* __restrict__ A, const __half* __restrict__ Bm,
            void* __restrict__ Cbase, int K, int lda, int ldb, int ldc)
{
    constexpr int BK = 32;
    constexpr int NW = (BM / WM) * (BN / WN);
    constexpr int NT = NW * 32;
    constexpr int MT = WM / 16;
    constexpr int NTI = WN / 8;
    constexpr int NST = 3;

    __shared__ __align__(16) __half As[NST][BM][BK];
    __shared__ __align__(16) __half Bs[NST][BN][BK];

    const int t = threadIdx.x;
    const int warp = t >> 5;
    const int lane = t & 31;
    const int group = lane >> 2;
    const int tg = lane & 3;
    const int wm = warp / (BN / WN);
    const int wn = warp % (BN / WN);
    const int m0 = blockIdx.y * BM;
    const int n0 = blockIdx.x * BN;

    const int nk = K / BK;

    auto prefetch = [&](int kt, int s) {
        const int k0 = kt * BK;
#pragma unroll
        for (int it = 0; it < (BM * 4) / NT; ++it) {
            int c = t + it * NT;
            int m = c >> 2, q = c & 3;
            cp_async16(&As[s][m][q * 8], &A[(long)(m0 + m) * lda + k0 + q * 8]);
        }
#pragma unroll
        for (int it = 0; it < (BN * 4) / NT; ++it) {
            int c = t + it * NT;
            int n = c >> 2, q = c & 3;
            cp_async16(&Bs[s][n][q * 8], &Bm[(long)(n0 + n) * ldb + k0 + q * 8]);
        }
        cp_commit();
    };

    float acc[MT][NTI][4];
#pragma unroll
    for (int i = 0; i < MT; i++)
#pragma unroll
        for (int j = 0; j < NTI; j++)
#pragma unroll
            for (int r = 0; r < 4; r++) acc[i][j][r] = 0.f;

    prefetch(0, 0);
    if (nk > 1) prefetch(1, 1); else cp_commit();

    for (int kt = 0; kt < nk; kt++) {
        const int s = kt % NST;
        if (kt + 2 < nk) prefetch(kt + 2, (kt + 2) % NST);
        else cp_commit();
        cp_wait<2>();
        __syncthreads();

        uint4 a4[MT][2];
        uint4 b4[NTI];
#pragma unroll
        for (int mt = 0; mt < MT; mt++) {
            int mr = wm * WM + mt * 16 + group;
            a4[mt][0] = *reinterpret_cast<const uint4*>(&As[s][mr][tg * 8]);
            a4[mt][1] = *reinterpret_cast<const uint4*>(&As[s][mr + 8][tg * 8]);
        }
#pragma unroll
        for (int nt = 0; nt < NTI; nt++) {
            int nc = wn * WN + nt * 8 + group;
            b4[nt] = *reinterpret_cast<const uint4*>(&Bs[s][nc][tg * 8]);
        }
#pragma unroll
        for (int mt = 0; mt < MT; mt++)
#pragma unroll
            for (int nt = 0; nt < NTI; nt++)
                mma_f16(acc[mt][nt], a4[mt][0].x, a4[mt][1].x, a4[mt][0].y, a4[mt][1].y,
                        b4[nt].x, b4[nt].y);
#pragma unroll
        for (int mt = 0; mt < MT; mt++)
#pragma unroll
            for (int nt = 0; nt < NTI; nt++)
                mma_f16(acc[mt][nt], a4[mt][0].z, a4[mt][1].z, a4[mt][0].w, a4[mt][1].w,
                        b4[nt].z, b4[nt].w);
        __syncthreads();
    }

#pragma unroll
    for (int mt = 0; mt < MT; mt++) {
#pragma unroll
        for (int nt = 0; nt < NTI; nt++) {
            int gm = m0 + wm * WM + mt * 16 + group;
            int gn = n0 + wn * WN + nt * 8 + tg * 2;
#pragma unroll
            for (int half = 0; half < 2; half++) {
                int row = gm + half * 8;
                float v0 = acc[mt][nt][half * 2 + 0];
                float v1 = acc[mt][nt][half * 2 + 1];
                if (EPI == E_RELUH) { v0 = fmaxf(v0, 0.f); v1 = fmaxf(v1, 0.f); }
                if (EPI == E_STOREF) {
                    float* C = (float*)Cbase;
                    float2 w; w.x = v0; w.y = v1;
                    *reinterpret_cast<float2*>(&C[(long)row * ldc + gn]) = w;
                } else {
                    __half* C = (__half*)Cbase;
                    *reinterpret_cast<__half2*>(&C[(long)row * ldc + gn]) =
                        __floats2half2_rn(v0, v1);
                }
            }
        }
    }
}

// ===========================================================================
// Pre-pass kernels
// ===========================================================================
__global__ __launch_bounds__(256) void hconv_k(const float* __restrict__ src,
                                               __half* __restrict__ dst, long n4)
{
    long i = (long)blockIdx.x * 256 + threadIdx.x;
    if (i >= n4) return;
    float4 v = reinterpret_cast<const float4*>(src)[i];
    __half2 h0 = __floats2half2_rn(v.x, v.y);
    __half2 h1 = __floats2half2_rn(v.z, v.w);
    uint2 u;
    u.x = *reinterpret_cast<uint32_t*>(&h0);
    u.y = *reinterpret_cast<uint32_t*>(&h1);
    reinterpret_cast<uint2*>(dst)[i] = u;
}

// dst[c*dld + r] = half(src[r*C + c])
__global__ __launch_bounds__(256) void htrans_k(const float* __restrict__ src,
                                                __half* __restrict__ dst,
                                                int R, int C, int dld)
{
    __shared__ float tile[32][33];
    int c0 = blockIdx.x * 32, r0 = blockIdx.y * 32;
    int tx = threadIdx.x & 31, ty = threadIdx.x >> 5;
    for (int i = ty; i < 32; i += 8)
        tile[i][tx] = src[(long)(r0 + i) * C + c0 + tx];
    __syncthreads();
    for (int i = ty; i < 32; i += 8)
        dst[(long)(c0 + i) * dld + r0 + tx] = __float2half(tile[tx][i]);
}

// KTh[bh][z][s] = Kh[b, s, h*64+z]
__global__ __launch_bounds__(256) void ktrans_h(const __half* __restrict__ K,
                                                __half* __restrict__ KT)
{
    __shared__ __half tile[32][33];
    int s0 = blockIdx.x * 32, z0 = blockIdx.y * 32, bh = blockIdx.z;
    int b = bh / Hc, h = bh % Hc;
    int tx = threadIdx.x & 31, ty = threadIdx.x >> 5;
    const __half* src = K + (long)b * Nc * Dc + h * Zc;
    for (int i = ty; i < 32; i += 8)
        tile[i][tx] = src[(long)(s0 + i) * Dc + z0 + tx];
    __syncthreads();
    __half* dst = KT + (long)bh * Zc * Nc;
    for (int i = ty; i < 32; i += 8)
        dst[(long)(z0 + i) * Nc + s0 + tx] = tile[tx][i];
}

// QsTh[bh][z][q] = Qh[b, q, h*64+z] * Zinv[bh][q]
__global__ __launch_bounds__(256) void qstrans_h(const __half* __restrict__ Q,
                                                 const float* __restrict__ zinv,
                                                 __half* __restrict__ QT)
{
    __shared__ __half tile[32][33];
    int s0 = blockIdx.x * 32, z0 = blockIdx.y * 32, bh = blockIdx.z;
    int b = bh / Hc, h = bh % Hc;
    int tx = threadIdx.x & 31, ty = threadIdx.x >> 5;
    const __half* src = Q + (long)b * Nc * Dc + h * Zc;
    const float* zv = zinv + (long)bh * Nc;
    for (int i = ty; i < 32; i += 8) {
        float v = __half2float(src[(long)(s0 + i) * Dc + z0 + tx]) * zv[s0 + i];
        tile[i][tx] = __float2half(v);
    }
    __syncthreads();
    __half* dst = QT + (long)bh * Zc * Nc;
    for (int i = ty; i < 32; i += 8)
        dst[(long)(z0 + i) * Nc + s0 + tx] = tile[tx][i];
}

// ===========================================================================
template <int BM, int BN, int WM, int WN, int EPI>
static void run_h(const __half* A, const __half* B, void* C,
                  int M, int N, int K, int lda, int ldb, int ldc)
{
    dim3 grid(N / BN, M / BM);
    gemm_h<BM, BN, WM, WN, EPI>
        <<<grid, (BM / WM) * (BN / WN) * 32>>>(A, B, C, K, lda, ldb, ldc);
}

extern "C" void kernel_launch(void* const* d_in, const int* in_sizes, int n_in,
                              void* d_out, int out_size)
{
    const float* x     = (const float*)d_in[0];
    const float* Wq    = (const float*)d_in[1];
    const float* Wk    = (const float*)d_in[2];
    const float* betas = (const float*)d_in[3];
    const float* Wmlp  = (const float*)d_in[4];
    float* out = (float*)d_out;

    __half *Qh, *Kh, *KTh, *QsTh, *AVh;
    __half *xh, *Wqh, *Wkh, *Wmlph, *WallTh;
    float *Zinv;
    cudaGetSymbolAddress((void**)&Qh,     g_Qh);
    cudaGetSymbolAddress((void**)&Kh,     g_Kh);
    cudaGetSymbolAddress((void**)&KTh,    g_KTh);
    cudaGetSymbolAddress((void**)&QsTh,   g_QsTh);
    cudaGetSymbolAddress((void**)&AVh,    g_AVh);
    cudaGetSymbolAddress((void**)&Zinv,   g_Zinv);
    cudaGetSymbolAddress((void**)&xh,     g_xh);
    cudaGetSymbolAddress((void**)&Wqh,    g_Wqh);
    cudaGetSymbolAddress((void**)&Wkh,    g_Wkh);
    cudaGetSymbolAddress((void**)&Wmlph,  g_Wmlph);
    cudaGetSymbolAddress((void**)&WallTh, g_WallTh);

    cudaFuncSetAttribute(fa_k<1>, cudaFuncAttributeMaxDynamicSharedMemorySize, fa::SMEM);
    cudaFuncSetAttribute(fa_k<0>, cudaFuncAttributeMaxDynamicSharedMemorySize, fa::SMEM);

    // ---- convert inputs to half; build stacked transposed weight Wall ----
    hconv_k<<<(Mrows * Dc / 4 + 255) / 256, 256>>>(x, xh, Mrows * Dc / 4);
    hconv_k<<<(Dc * Dc / 4 + 255) / 256, 256>>>(Wq, Wqh, Dc * Dc / 4);
    hconv_k<<<(Dc * Dc / 4 + 255) / 256, 256>>>(Wk, Wkh, Dc * Dc / 4);
    hconv_k<<<(HIDc * Dc / 4 + 255) / 256, 256>>>(Wmlp, Wmlph, HIDc * Dc / 4);
    // Wall[n=d][k]: cols 0:768 = Wq^T, 768:1536 = Wk^T, 1536:4608 = Wmlp^T
    htrans_k<<<dim3(Dc / 32, Dc / 32), 256>>>(Wq, WallTh, Dc, Dc, KC);
    htrans_k<<<dim3(Dc / 32, Dc / 32), 256>>>(Wk, WallTh + Dc, Dc, Dc, KC);
    htrans_k<<<dim3(Dc / 32, HIDc / 32), 256>>>(Wmlp, WallTh + 2 * Dc, HIDc, Dc, KC);

    // 1) Q = x @ Wq^T ; K = x @ Wk^T ; hid = relu(x @ Wmlp^T) -> AVh[:,1536:]
    run_h<128, 128, 64, 64, E_STOREH>(xh, Wqh, Qh, Mrows, Dc, Dc, Dc, Dc, Dc);
    run_h<128, 128, 64, 64, E_STOREH>(xh, Wkh, Kh, Mrows, Dc, Dc, Dc, Dc, Dc);
    run_h<128, 128, 64, 64, E_RELUH>(xh, Wmlph, AVh + 2 * Dc, Mrows, HIDc, Dc, Dc, Dc, KC);

    ktrans_h<<<dim3(Nc / 32, Zc / 32, Bc * Hc), 256>>>(Kh, KTh);

    // 2) FA1: AV1 -> AVh[:,0:768], Zinv inline
    fa_k<1><<<dim3(Nc / 128, Bc * Hc), 256, fa::SMEM>>>(Qh, Kh, KTh, AVh, KC, Zinv, betas);

    // 3) Qs = diag(Zinv) Q transposed; FA2: AV2 -> AVh[:,768:1536]
    qstrans_h<<<dim3(Nc / 32, Zc / 32, Bc * Hc), 256>>>(Qh, Zinv, QsTh);
    fa_k<0><<<dim3(Nc / 128, Bc * Hc), 256, fa::SMEM>>>(Kh, Qh, QsTh, AVh + Dc, KC, Zinv, betas);

    // 4) out = [AV1|AV2|hid] @ Wall  (single K=4608 GEMM, fp32 out)
    run_h<128, 128, 64, 64, E_STOREF>(AVh, WallTh, out, Mrows, Dc, KC, KC, KC, Dc);
}

// round 12
// speedup vs baseline: 1.2227x; 1.0151x over previous
#include <cuda_runtime.h>
#include <cuda_fp16.h>
#include <cstdint>

// ---------------------------------------------------------------------------
// KQEnergyBlock: B=8, N=1024, D=768, H=12, Z=64, HID=3072
//   [Q|K|hid] = x @ [Wq;Wk;Wmlp]^T  (ONE projection GEMM, epilogue routing)
//   FA1 (64-row tiles): S=Q K^T, Pu=exp(beta S), AV1=Zinv*(Pu K), Zinv inline
//   FA2: S^T, Pu^T, AV2 = Pu^T (Zinv Q)
//   out = [AV1|AV2|hid] @ [Wq;Wk;Wmlp]-stacked  (single K=4608 GEMM)
// ---------------------------------------------------------------------------

namespace {
constexpr int Bc = 8, Nc = 1024, Dc = 768, Hc = 12, Zc = 64, HIDc = 3072;
constexpr int Mrows = Bc * Nc;    // 8192
constexpr int D2 = 2 * Dc;        // 1536
constexpr int KC = 2 * Dc + HIDc; // 4608
}

__device__ __align__(16) __half g_QKh[(size_t)Mrows * D2];      // [Q|K]
__device__ __align__(16) __half g_KTh[(size_t)Bc * Hc * Zc * Nc];
__device__ __align__(16) __half g_QsTh[(size_t)Bc * Hc * Zc * Nc];
__device__ __align__(16) __half g_AVh[(size_t)Mrows * KC];      // [AV1|AV2|hid]
__device__ __align__(16) float  g_Zinv[(size_t)Bc * Hc * Nc];
__device__ __align__(16) __half g_xh[Mrows * Dc];
__device__ __align__(16) __half g_WcatH[(size_t)KC * Dc];       // rows: Wq|Wk|Wmlp
__device__ __align__(16) __half g_WallTh[(size_t)Dc * KC];      // [d][e|e'|h]

enum { E_STOREF = 0, E_PROJ = 1 };

__device__ __forceinline__ void cp_async16(void* smem_dst, const void* gmem_src) {
    uint32_t sa = (uint32_t)__cvta_generic_to_shared(smem_dst);
    asm volatile("cp.async.cg.shared.global [%0], [%1], 16;\n" :: "r"(sa), "l"(gmem_src));
}
__device__ __forceinline__ void cp_commit() {
    asm volatile("cp.async.commit_group;\n");
}
template <int Nw>
__device__ __forceinline__ void cp_wait() {
    asm volatile("cp.async.wait_group %0;\n" :: "n"(Nw));
}

__device__ __forceinline__ void mma_f16(float c[4],
                                        uint32_t a0, uint32_t a1, uint32_t a2, uint32_t a3,
                                        uint32_t b0, uint32_t b1) {
    asm volatile(
        "mma.sync.aligned.m16n8k16.row.col.f32.f16.f16.f32 "
        "{%0,%1,%2,%3}, {%4,%5,%6,%7}, {%8,%9}, {%0,%1,%2,%3};\n"
        : "+f"(c[0]), "+f"(c[1]), "+f"(c[2]), "+f"(c[3])
        : "r"(a0), "r"(a1), "r"(a2), "r"(a3), "r"(b0), "r"(b1));
}

// ===========================================================================
// Fused flash attention, 64 output rows per CTA, 256 threads / 8 warps,
// exp overlapped with previous AV-mma.
// smem: Rt[2]8K | Ct[4][2]64K | T2[4][4]64K | P[2][4]32K | red 1K | zs .25K
// ===========================================================================
namespace fa {
constexpr int OFF_R   = 0;
constexpr int OFF_C   = 8192;
constexpr int OFF_T2  = 73728;
constexpr int OFF_P   = 139264;
constexpr int OFF_RED = 172032;
constexpr int OFF_ZS  = 173056;
constexpr int SMEM    = 173312;
}

template <int DO_ZINV>
__global__ __launch_bounds__(256, 1)
void fa_k(const __half* __restrict__ Rbase, int ldr,
          const __half* __restrict__ Cbase, int ldcc,
          const __half* __restrict__ T2base, __half* __restrict__ Outbase,
          int ldo, float* __restrict__ zinvg, const float* __restrict__ betas)
{
    extern __shared__ __align__(16) char smem[];
    __half (*Rt)[64][32]      = reinterpret_cast<__half(*)[64][32]>(smem + fa::OFF_R);
    __half (*Ct)[2][128][32]  = reinterpret_cast<__half(*)[2][128][32]>(smem + fa::OFF_C);
    __half (*T2)[4][64][32]   = reinterpret_cast<__half(*)[4][64][32]>(smem + fa::OFF_T2);
    __half (*P)[4][64][32]    = reinterpret_cast<__half(*)[4][64][32]>(smem + fa::OFF_P);
    float (*red)[64]          = reinterpret_cast<float(*)[64]>(smem + fa::OFF_RED);
    float* zs                 = reinterpret_cast<float*>(smem + fa::OFF_ZS);

    const int bh = blockIdx.y;
    const int b = bh / Hc, hi = bh % Hc;
    const int blk = blockIdx.x;
    const float beta = betas[hi];

    const __half* Rb = Rbase + ((long)b * Nc + blk * 64) * ldr + hi * Zc;
    const __half* Cb = Cbase + (long)b * Nc * ldcc + hi * Zc;
    const __half* T2b = T2base + (long)bh * Zc * Nc;
    __half* Outb = Outbase + ((long)b * Nc + blk * 64) * ldo + hi * Zc;

    const int tid = threadIdx.x;
    const int warp = tid >> 5;
    const int lane = tid & 31;
    const int group = lane >> 2;
    const int tg = lane & 3;
    const int wq = warp >> 2;   // 0..1
    const int wk = warp & 3;    // 0..3

    auto loadC = [&](int it2, int s) {
#pragma unroll
        for (int i = 0; i < 4; i++) {
            int c = tid + i * 256;
            int m = c >> 3, r = c & 7;
            int zc = r >> 2, q = r & 3;
            cp_async16(&Ct[s][zc][m][q * 8],
                       &Cb[(long)(it2 * 128 + m) * ldcc + zc * 32 + q * 8]);
        }
#pragma unroll
        for (int i = 0; i < 4; i++) {
            int c = tid + i * 256;
            int kc = c >> 8, rem = c & 255;
            int z = rem >> 2, q = rem & 3;
            cp_async16(&T2[s][kc][z][q * 8],
                       &T2b[(long)z * Nc + it2 * 128 + kc * 32 + q * 8]);
        }
        cp_commit();
    };

    {   // prefetch R block + iter0, then iter1
#pragma unroll
        for (int i = 0; i < 2; i++) {
            int c = tid + i * 256;
            int m = c >> 3, r = c & 7;
            int zc = r >> 2, q = r & 3;
            cp_async16(&Rt[zc][m][q * 8], &Rb[(long)m * ldr + zc * 32 + q * 8]);
        }
        loadC(0, 0);
        loadC(1, 1);
    }

    float av[2][2][4];
#pragma unroll
    for (int i = 0; i < 2; i++)
#pragma unroll
        for (int j = 0; j < 2; j++)
#pragma unroll
            for (int r = 0; r < 4; r++) av[i][j][r] = 0.f;
    float rs[2][2];
    if (DO_ZINV) {
#pragma unroll
        for (int i = 0; i < 2; i++) { rs[i][0] = 0.f; rs[i][1] = 0.f; }
    }

    for (int it = 0; it < 8; it++) {
        const int s = it & 3;
        if (it + 2 < 8) loadC(it + 2, (it + 2) & 3);
        else cp_commit();
        cp_wait<2>();
        __syncthreads();

        // ---- S(it) = R @ C^T  (warp tile 32q x 32k) ----
        float sacc[2][4][4];
#pragma unroll
        for (int i = 0; i < 2; i++)
#pragma unroll
            for (int j = 0; j < 4; j++)
#pragma unroll
                for (int r = 0; r < 4; r++) sacc[i][j][r] = 0.f;

#pragma unroll
        for (int zc = 0; zc < 2; zc++) {
            uint4 a[2][2];
#pragma unroll
            for (int mt = 0; mt < 2; mt++) {
                int mr = wq * 32 + mt * 16 + group;
                a[mt][0] = *reinterpret_cast<const uint4*>(&Rt[zc][mr][tg * 8]);
                a[mt][1] = *reinterpret_cast<const uint4*>(&Rt[zc][mr + 8][tg * 8]);
            }
#pragma unroll
            for (int nt = 0; nt < 4; nt++) {
                int nc = wk * 32 + nt * 8 + group;
                uint4 bb = *reinterpret_cast<const uint4*>(&Ct[s][zc][nc][tg * 8]);
#pragma unroll
                for (int mt = 0; mt < 2; mt++) {
                    mma_f16(sacc[mt][nt], a[mt][0].x, a[mt][1].x, a[mt][0].y, a[mt][1].y,
                            bb.x, bb.y);
                    mma_f16(sacc[mt][nt], a[mt][0].z, a[mt][1].z, a[mt][0].w, a[mt][1].w,
                            bb.z, bb.w);
                }
            }
        }

        // ---- interleave: AV(it-1) mma + exp(it) -> P[pcur] ----
        const int pcur = it & 1;
        const int pprev = pcur ^ 1;
        const int sprev = (it + 3) & 3;

#pragma unroll
        for (int j = 0; j < 4; j++) {
            if (it > 0) {
                uint4 a[2][2];
#pragma unroll
                for (int mt = 0; mt < 2; mt++) {
                    int mr = wq * 32 + mt * 16 + group;
                    a[mt][0] = *reinterpret_cast<const uint4*>(&P[pprev][j][mr][tg * 8]);
                    a[mt][1] = *reinterpret_cast<const uint4*>(&P[pprev][j][mr + 8][tg * 8]);
                }
#pragma unroll
                for (int nt = 0; nt < 2; nt++) {
                    int nc = wk * 16 + nt * 8 + group;
                    uint4 bb = *reinterpret_cast<const uint4*>(&T2[sprev][j][nc][tg * 8]);
#pragma unroll
                    for (int mt = 0; mt < 2; mt++) {
                        mma_f16(av[mt][nt], a[mt][0].x, a[mt][1].x, a[mt][0].y, a[mt][1].y,
                                bb.x, bb.y);
                        mma_f16(av[mt][nt], a[mt][0].z, a[mt][1].z, a[mt][0].w, a[mt][1].w,
                                bb.z, bb.w);
                    }
                }
            }
#pragma unroll
            for (int mt = 0; mt < 2; mt++) {
                int r0 = wq * 32 + mt * 16 + group;
                float v0 = __expf(beta * sacc[mt][j][0]);
                float v1 = __expf(beta * sacc[mt][j][1]);
                float v2 = __expf(beta * sacc[mt][j][2]);
                float v3 = __expf(beta * sacc[mt][j][3]);
                if (DO_ZINV) { rs[mt][0] += v0 + v1; rs[mt][1] += v2 + v3; }
                int colw = j * 8 + tg * 2;
                *reinterpret_cast<__half2*>(&P[pcur][wk][r0][colw]) =
                    __floats2half2_rn(v0, v1);
                *reinterpret_cast<__half2*>(&P[pcur][wk][r0 + 8][colw]) =
                    __floats2half2_rn(v2, v3);
            }
        }
        __syncthreads();
    }

    // ---- epilogue: AV(7) (P buf 1, T2 stage 3) ----
#pragma unroll
    for (int j = 0; j < 4; j++) {
        uint4 a[2][2];
#pragma unroll
        for (int mt = 0; mt < 2; mt++) {
            int mr = wq * 32 + mt * 16 + group;
            a[mt][0] = *reinterpret_cast<const uint4*>(&P[1][j][mr][tg * 8]);
            a[mt][1] = *reinterpret_cast<const uint4*>(&P[1][j][mr + 8][tg * 8]);
        }
#pragma unroll
        for (int nt = 0; nt < 2; nt++) {
            int nc = wk * 16 + nt * 8 + group;
            uint4 bb = *reinterpret_cast<const uint4*>(&T2[3][j][nc][tg * 8]);
#pragma unroll
            for (int mt = 0; mt < 2; mt++) {
                mma_f16(av[mt][nt], a[mt][0].x, a[mt][1].x, a[mt][0].y, a[mt][1].y,
                        bb.x, bb.y);
                mma_f16(av[mt][nt], a[mt][0].z, a[mt][1].z, a[mt][0].w, a[mt][1].w,
                        bb.z, bb.w);
            }
        }
    }

    // ---- Zinv (FA1 only) ----
    if (DO_ZINV) {
#pragma unroll
        for (int mt = 0; mt < 2; mt++) {
#pragma unroll
            for (int h = 0; h < 2; h++) {
                float v = rs[mt][h];
                v += __shfl_xor_sync(0xffffffffu, v, 1);
                v += __shfl_xor_sync(0xffffffffu, v, 2);
                if (tg == 0)
                    red[wk][wq * 32 + mt * 16 + h * 8 + group] = v;
            }
        }
        __syncthreads();
        if (tid < 64) {
            float ssum = red[0][tid] + red[1][tid] + red[2][tid] + red[3][tid];
            float zi = 1.f / ssum;
            zs[tid] = zi;
            zinvg[(long)bh * Nc + blk * 64 + tid] = zi;
        }
        __syncthreads();
    }

    // ---- store AV ----
#pragma unroll
    for (int mt = 0; mt < 2; mt++) {
#pragma unroll
        for (int nt = 0; nt < 2; nt++) {
            int col = wk * 16 + nt * 8 + tg * 2;
#pragma unroll
            for (int h = 0; h < 2; h++) {
                int row = wq * 32 + mt * 16 + h * 8 + group;
                float v0 = av[mt][nt][h * 2 + 0];
                float v1 = av[mt][nt][h * 2 + 1];
                if (DO_ZINV) {
                    float zi = zs[row];
                    v0 *= zi; v1 *= zi;
                }
                *reinterpret_cast<__half2*>(&Outb[(long)row * ldo + col]) =
                    __floats2half2_rn(v0, v1);
            }
        }
    }
}

// ===========================================================================
// Dense half GEMM: C = A[m][k] @ B[n][k]^T.
// E_PROJ: gn < 1536 -> QK half buffer (ld D2); gn >= 1536 -> relu -> C2 (ld KC).
// E_STOREF: fp32 store to C (ld ldc).
// ===========================================================================
template <int BM, int BN, int WM, int WN, int EPI>
__global__ __launch_bounds__((BM / WM) * (BN / WN) * 32)
void gemm_h(const __half* __restrict__ A, const __half* __restrict__ Bm,
            void* __restrict__ Cbase, void* __restrict__ C2base,
            int K, int lda, int ldb, int ldc)
{
    constexpr int BK = 32;
    constexpr int NW = (BM / WM) * (BN / WN);
    constexpr int NT = NW * 32;
    constexpr int MT = WM / 16;
    constexpr int NTI = WN / 8;
    constexpr int NST = 3;

    __shared__ __align__(16) __half As[NST][BM][BK];
    __shared__ __align__(16) __half Bs[NST][BN][BK];

    const int t = threadIdx.x;
    const int warp = t >> 5;
    const int lane = t & 31;
    const int group = lane >> 2;
    const int tg = lane & 3;
    const int wm = warp / (BN / WN);
    const int wn = warp % (BN / WN);
    const int m0 = blockIdx.y * BM;
    const int n0 = blockIdx.x * BN;

    const int nk = K / BK;

    auto prefetch = [&](int kt, int s) {
        const int k0 = kt * BK;
#pragma unroll
        for (int it = 0; it < (BM * 4) / NT; ++it) {
            int c = t + it * NT;
            int m = c >> 2, q = c & 3;
            cp_async16(&As[s][m][q * 8], &A[(long)(m0 + m) * lda + k0 + q * 8]);
        }
#pragma unroll
        for (int it = 0; it < (BN * 4) / NT; ++it) {
            int c = t + it * NT;
            int n = c >> 2, q = c & 3;
            cp_async16(&Bs[s][n][q * 8], &Bm[(long)(n0 + n) * ldb + k0 + q * 8]);
        }
        cp_commit();
    };

    float acc[MT][NTI][4];
#pragma unroll
    for (int i = 0; i < MT; i++)
#pragma unroll
        for (int j = 0; j < NTI; j++)
#pragma unroll
            for (int r = 0; r < 4; r++) acc[i][j][r] = 0.f;

    prefetch(0, 0);
    if (nk > 1) prefetch(1, 1); else cp_commit();

    for (int kt = 0; kt < nk; kt++) {
        const int s = kt % NST;
        if (kt + 2 < nk) prefetch(kt + 2, (kt + 2) % NST);
        else cp_commit();
        cp_wait<2>();
        __syncthreads();

        uint4 a4[MT][2];
        uint4 b4[NTI];
#pragma unroll
        for (int mt = 0; mt < MT; mt++) {
            int mr = wm * WM + mt * 16 + group;
            a4[mt][0] = *reinterpret_cast<const uint4*>(&As[s][mr][tg * 8]);
            a4[mt][1] = *reinterpret_cast<const uint4*>(&As[s][mr + 8][tg * 8]);
        }
#pragma unroll
        for (int nt = 0; nt < NTI; nt++) {
            int nc = wn * WN + nt * 8 + group;
            b4[nt] = *reinterpret_cast<const uint4*>(&Bs[s][nc][tg * 8]);
        }
#pragma unroll
        for (int mt = 0; mt < MT; mt++)
#pragma unroll
            for (int nt = 0; nt < NTI; nt++)
                mma_f16(acc[mt][nt], a4[mt][0].x, a4[mt][1].x, a4[mt][0].y, a4[mt][1].y,
                        b4[nt].x, b4[nt].y);
#pragma unroll
        for (int mt = 0; mt < MT; mt++)
#pragma unroll
            for (int nt = 0; nt < NTI; nt++)
                mma_f16(acc[mt][nt], a4[mt][0].z, a4[mt][1].z, a4[mt][0].w, a4[mt][1].w,
                        b4[nt].z, b4[nt].w);
        __syncthreads();
    }

#pragma unroll
    for (int mt = 0; mt < MT; mt++) {
#pragma unroll
        for (int nt = 0; nt < NTI; nt++) {
            int gm = m0 + wm * WM + mt * 16 + group;
            int gn = n0 + wn * WN + nt * 8 + tg * 2;
#pragma unroll
            for (int half = 0; half < 2; half++) {
                int row = gm + half * 8;
                float v0 = acc[mt][nt][half * 2 + 0];
                float v1 = acc[mt][nt][half * 2 + 1];
                if (EPI == E_PROJ) {
                    if (gn < D2) {
                        __half* C = (__half*)Cbase;
                        *reinterpret_cast<__half2*>(&C[(long)row * D2 + gn]) =
                            __floats2half2_rn(v0, v1);
                    } else {
                        v0 = fmaxf(v0, 0.f); v1 = fmaxf(v1, 0.f);
                        __half* C2 = (__half*)C2base;
                        *reinterpret_cast<__half2*>(&C2[(long)row * KC + gn]) =
                            __floats2half2_rn(v0, v1);
                    }
                } else {
                    float* C = (float*)Cbase;
                    float2 w; w.x = v0; w.y = v1;
                    *reinterpret_cast<float2*>(&C[(long)row * ldc + gn]) = w;
                }
            }
        }
    }
}

// ===========================================================================
// Pre-pass kernels
// ===========================================================================
__global__ __launch_bounds__(256) void hconv_k(const float* __restrict__ src,
                                               __half* __restrict__ dst, long n4)
{
    long i = (long)blockIdx.x * 256 + threadIdx.x;
    if (i >= n4) return;
    float4 v = reinterpret_cast<const float4*>(src)[i];
    __half2 h0 = __floats2half2_rn(v.x, v.y);
    __half2 h1 = __floats2half2_rn(v.z, v.w);
    uint2 u;
    u.x = *reinterpret_cast<uint32_t*>(&h0);
    u.y = *reinterpret_cast<uint32_t*>(&h1);
    reinterpret_cast<uint2*>(dst)[i] = u;
}

// dst[c*dld + r] = half(src[r*C + c])
__global__ __launch_bounds__(256) void htrans_k(const float* __restrict__ src,
                                                __half* __restrict__ dst,
                                                int R, int C, int dld)
{
    __shared__ float tile[32][33];
    int c0 = blockIdx.x * 32, r0 = blockIdx.y * 32;
    int tx = threadIdx.x & 31, ty = threadIdx.x >> 5;
    for (int i = ty; i < 32; i += 8)
        tile[i][tx] = src[(long)(r0 + i) * C + c0 + tx];
    __syncthreads();
    for (int i = ty; i < 32; i += 8)
        dst[(long)(c0 + i) * dld + r0 + tx] = __float2half(tile[tx][i]);
}

// KT[bh][z][s] = src0[b*Nc*ldk + s*ldk + h*64 + z]
__global__ __launch_bounds__(256) void ktrans_h(const __half* __restrict__ src0,
                                                int ldk, __half* __restrict__ KT)
{
    __shared__ __half tile[32][33];
    int s0 = blockIdx.x * 32, z0 = blockIdx.y * 32, bh = blockIdx.z;
    int b = bh / Hc, h = bh % Hc;
    int tx = threadIdx.x & 31, ty = threadIdx.x >> 5;
    const __half* src = src0 + (long)b * Nc * ldk + h * Zc;
    for (int i = ty; i < 32; i += 8)
        tile[i][tx] = src[(long)(s0 + i) * ldk + z0 + tx];
    __syncthreads();
    __half* dst = KT + (long)bh * Zc * Nc;
    for (int i = ty; i < 32; i += 8)
        dst[(long)(z0 + i) * Nc + s0 + tx] = tile[tx][i];
}

// QsT[bh][z][q] = src0[b*Nc*ldq + q*ldq + h*64 + z] * Zinv[bh][q]
__global__ __launch_bounds__(256) void qstrans_h(const __half* __restrict__ src0,
                                                 int ldq,
                                                 const float* __restrict__ zinv,
                                                 __half* __restrict__ QT)
{
    __shared__ __half tile[32][33];
    int s0 = blockIdx.x * 32, z0 = blockIdx.y * 32, bh = blockIdx.z;
    int b = bh / Hc, h = bh % Hc;
    int tx = threadIdx.x & 31, ty = threadIdx.x >> 5;
    const __half* src = src0 + (long)b * Nc * ldq + h * Zc;
    const float* zv = zinv + (long)bh * Nc;
    for (int i = ty; i < 32; i += 8) {
        float v = __half2float(src[(long)(s0 + i) * ldq + z0 + tx]) * zv[s0 + i];
        tile[i][tx] = __float2half(v);
    }
    __syncthreads();
    __half* dst = QT + (long)bh * Zc * Nc;
    for (int i = ty; i < 32; i += 8)
        dst[(long)(z0 + i) * Nc + s0 + tx] = tile[tx][i];
}

// ===========================================================================
template <int BM, int BN, int WM, int WN, int EPI>
static void run_h(const __half* A, const __half* B, void* C, void* C2,
                  int M, int N, int K, int lda, int ldb, int ldc)
{
    dim3 grid(N / BN, M / BM);
    gemm_h<BM, BN, WM, WN, EPI>
        <<<grid, (BM / WM) * (BN / WN) * 32>>>(A, B, C, C2, K, lda, ldb, ldc);
}

extern "C" void kernel_launch(void* const* d_in, const int* in_sizes, int n_in,
                              void* d_out, int out_size)
{
    const float* x     = (const float*)d_in[0];
    const float* Wq    = (const float*)d_in[1];
    const float* Wk    = (const float*)d_in[2];
    const float* betas = (const float*)d_in[3];
    const float* Wmlp  = (const float*)d_in[4];
    float* out = (float*)d_out;

    __half *QKh, *KTh, *QsTh, *AVh, *xh, *WcatH, *WallTh;
    float *Zinv;
    cudaGetSymbolAddress((void**)&QKh,    g_QKh);
    cudaGetSymbolAddress((void**)&KTh,    g_KTh);
    cudaGetSymbolAddress((void**)&QsTh,   g_QsTh);
    cudaGetSymbolAddress((void**)&AVh,    g_AVh);
    cudaGetSymbolAddress((void**)&Zinv,   g_Zinv);
    cudaGetSymbolAddress((void**)&xh,     g_xh);
    cudaGetSymbolAddress((void**)&WcatH,  g_WcatH);
    cudaGetSymbolAddress((void**)&WallTh, g_WallTh);

    cudaFuncSetAttribute(fa_k<1>, cudaFuncAttributeMaxDynamicSharedMemorySize, fa::SMEM);
    cudaFuncSetAttribute(fa_k<0>, cudaFuncAttributeMaxDynamicSharedMemorySize, fa::SMEM);

    // ---- half conversions: x, stacked weight rows [Wq;Wk;Wmlp] ----
    hconv_k<<<(Mrows * Dc / 4 + 255) / 256, 256>>>(x, xh, Mrows * Dc / 4);
    hconv_k<<<(Dc * Dc / 4 + 255) / 256, 256>>>(Wq, WcatH, Dc * Dc / 4);
    hconv_k<<<(Dc * Dc / 4 + 255) / 256, 256>>>(Wk, WcatH + (size_t)Dc * Dc, Dc * Dc / 4);
    hconv_k<<<(HIDc * Dc / 4 + 255) / 256, 256>>>(Wmlp, WcatH + (size_t)D2 * Dc,
                                                  HIDc * Dc / 4);
    // stacked transposed weight for final GEMM
    htrans_k<<<dim3(Dc / 32, Dc / 32), 256>>>(Wq, WallTh, Dc, Dc, KC);
    htrans_k<<<dim3(Dc / 32, Dc / 32), 256>>>(Wk, WallTh + Dc, Dc, Dc, KC);
    htrans_k<<<dim3(Dc / 32, HIDc / 32), 256>>>(Wmlp, WallTh + D2, HIDc, Dc, KC);

    // 1) [Q|K|hid] = x @ Wcat^T  (one GEMM; hid -> AVh cols 1536:4608, relu)
    run_h<128, 128, 64, 64, E_PROJ>(xh, WcatH, QKh, AVh,
                                    Mrows, KC, Dc, Dc, Dc, 0);

    // KT for FA1's T2 operand (K = QKh cols 768:1536)
    ktrans_h<<<dim3(Nc / 32, Zc / 32, Bc * Hc), 256>>>(QKh + Dc, D2, KTh);

    // 2) FA1: AV1 -> AVh[:,0:768], Zinv inline  (R=Q, C=K, T2=KT)
    fa_k<1><<<dim3(Nc / 64, Bc * Hc), 256, fa::SMEM>>>(
        QKh, D2, QKh + Dc, D2, KTh, AVh, KC, Zinv, betas);

    // 3) QsT = diag(Zinv) Q transposed; FA2: AV2 -> AVh[:,768:1536]
    qstrans_h<<<dim3(Nc / 32, Zc / 32, Bc * Hc), 256>>>(QKh, D2, Zinv, QsTh);
    fa_k<0><<<dim3(Nc / 64, Bc * Hc), 256, fa::SMEM>>>(
        QKh + Dc, D2, QKh, D2, QsTh, AVh + Dc, KC, Zinv, betas);

    // 4) out = [AV1|AV2|hid] @ Wall  (single K=4608 GEMM, fp32 out)
    run_h<128, 128, 64, 64, E_STOREF>(AVh, WallTh, out, nullptr,
                                      Mrows, Dc, KC, KC, KC, Dc);
}

// round 14
// speedup vs baseline: 1.2772x; 1.0446x over previous
#include <cuda_runtime.h>
#include <cuda_fp16.h>
#include <cstdint>

// ---------------------------------------------------------------------------
// KQEnergyBlock: B=8, N=1024, D=768, H=12, Z=64, HID=3072
//   [Q|K|hid] = x @ [Wq;Wk;Wmlp]^T  (ONE projection GEMM, epilogue routing)
//   FA1 (64-row tiles): S=Q K^T, Pu=exp(beta S), AV1=Zinv*(Pu K), Zinv inline
//   FA2: S^T, Pu^T, AV2 = Pu^T (Zinv Q)
//   out = [AV1|AV2|hid] @ [Wq;Wk;Wmlp]-stacked  (single K=4608 GEMM)
// R13: dense GEMM BK=64 (chunked smem, conflict-free), halved barrier count.
// ---------------------------------------------------------------------------

namespace {
constexpr int Bc = 8, Nc = 1024, Dc = 768, Hc = 12, Zc = 64, HIDc = 3072;
constexpr int Mrows = Bc * Nc;    // 8192
constexpr int D2 = 2 * Dc;        // 1536
constexpr int KC = 2 * Dc + HIDc; // 4608
}

__device__ __align__(16) __half g_QKh[(size_t)Mrows * D2];      // [Q|K]
__device__ __align__(16) __half g_KTh[(size_t)Bc * Hc * Zc * Nc];
__device__ __align__(16) __half g_QsTh[(size_t)Bc * Hc * Zc * Nc];
__device__ __align__(16) __half g_AVh[(size_t)Mrows * KC];      // [AV1|AV2|hid]
__device__ __align__(16) float  g_Zinv[(size_t)Bc * Hc * Nc];
__device__ __align__(16) __half g_xh[Mrows * Dc];
__device__ __align__(16) __half g_WcatH[(size_t)KC * Dc];       // rows: Wq|Wk|Wmlp
__device__ __align__(16) __half g_WallTh[(size_t)Dc * KC];      // [d][e|e'|h]

enum { E_STOREF = 0, E_PROJ = 1 };

__device__ __forceinline__ void cp_async16(void* smem_dst, const void* gmem_src) {
    uint32_t sa = (uint32_t)__cvta_generic_to_shared(smem_dst);
    asm volatile("cp.async.cg.shared.global [%0], [%1], 16;\n" :: "r"(sa), "l"(gmem_src));
}
__device__ __forceinline__ void cp_commit() {
    asm volatile("cp.async.commit_group;\n");
}
template <int Nw>
__device__ __forceinline__ void cp_wait() {
    asm volatile("cp.async.wait_group %0;\n" :: "n"(Nw));
}

__device__ __forceinline__ void mma_f16(float c[4],
                                        uint32_t a0, uint32_t a1, uint32_t a2, uint32_t a3,
                                        uint32_t b0, uint32_t b1) {
    asm volatile(
        "mma.sync.aligned.m16n8k16.row.col.f32.f16.f16.f32 "
        "{%0,%1,%2,%3}, {%4,%5,%6,%7}, {%8,%9}, {%0,%1,%2,%3};\n"
        : "+f"(c[0]), "+f"(c[1]), "+f"(c[2]), "+f"(c[3])
        : "r"(a0), "r"(a1), "r"(a2), "r"(a3), "r"(b0), "r"(b1));
}

// ===========================================================================
// Fused flash attention (unchanged from R12), 64 output rows per CTA.
// ===========================================================================
namespace fa {
constexpr int OFF_R   = 0;
constexpr int OFF_C   = 8192;
constexpr int OFF_T2  = 73728;
constexpr int OFF_P   = 139264;
constexpr int OFF_RED = 172032;
constexpr int OFF_ZS  = 173056;
constexpr int SMEM    = 173312;
}

template <int DO_ZINV>
__global__ __launch_bounds__(256, 1)
void fa_k(const __half* __restrict__ Rbase, int ldr,
          const __half* __restrict__ Cbase, int ldcc,
          const __half* __restrict__ T2base, __half* __restrict__ Outbase,
          int ldo, float* __restrict__ zinvg, const float* __restrict__ betas)
{
    extern __shared__ __align__(16) char smem[];
    __half (*Rt)[64][32]      = reinterpret_cast<__half(*)[64][32]>(smem + fa::OFF_R);
    __half (*Ct)[2][128][32]  = reinterpret_cast<__half(*)[2][128][32]>(smem + fa::OFF_C);
    __half (*T2)[4][64][32]   = reinterpret_cast<__half(*)[4][64][32]>(smem + fa::OFF_T2);
    __half (*P)[4][64][32]    = reinterpret_cast<__half(*)[4][64][32]>(smem + fa::OFF_P);
    float (*red)[64]          = reinterpret_cast<float(*)[64]>(smem + fa::OFF_RED);
    float* zs                 = reinterpret_cast<float*>(smem + fa::OFF_ZS);

    const int bh = blockIdx.y;
    const int b = bh / Hc, hi = bh % Hc;
    const int blk = blockIdx.x;
    const float beta = betas[hi];

    const __half* Rb = Rbase + ((long)b * Nc + blk * 64) * ldr + hi * Zc;
    const __half* Cb = Cbase + (long)b * Nc * ldcc + hi * Zc;
    const __half* T2b = T2base + (long)bh * Zc * Nc;
    __half* Outb = Outbase + ((long)b * Nc + blk * 64) * ldo + hi * Zc;

    const int tid = threadIdx.x;
    const int warp = tid >> 5;
    const int lane = tid & 31;
    const int group = lane >> 2;
    const int tg = lane & 3;
    const int wq = warp >> 2;
    const int wk = warp & 3;

    auto loadC = [&](int it2, int s) {
#pragma unroll
        for (int i = 0; i < 4; i++) {
            int c = tid + i * 256;
            int m = c >> 3, r = c & 7;
            int zc = r >> 2, q = r & 3;
            cp_async16(&Ct[s][zc][m][q * 8],
                       &Cb[(long)(it2 * 128 + m) * ldcc + zc * 32 + q * 8]);
        }
#pragma unroll
        for (int i = 0; i < 4; i++) {
            int c = tid + i * 256;
            int kc = c >> 8, rem = c & 255;
            int z = rem >> 2, q = rem & 3;
            cp_async16(&T2[s][kc][z][q * 8],
                       &T2b[(long)z * Nc + it2 * 128 + kc * 32 + q * 8]);
        }
        cp_commit();
    };

    {
#pragma unroll
        for (int i = 0; i < 2; i++) {
            int c = tid + i * 256;
            int m = c >> 3, r = c & 7;
            int zc = r >> 2, q = r & 3;
            cp_async16(&Rt[zc][m][q * 8], &Rb[(long)m * ldr + zc * 32 + q * 8]);
        }
        loadC(0, 0);
        loadC(1, 1);
    }

    float av[2][2][4];
#pragma unroll
    for (int i = 0; i < 2; i++)
#pragma unroll
        for (int j = 0; j < 2; j++)
#pragma unroll
            for (int r = 0; r < 4; r++) av[i][j][r] = 0.f;
    float rs[2][2];
    if (DO_ZINV) {
#pragma unroll
        for (int i = 0; i < 2; i++) { rs[i][0] = 0.f; rs[i][1] = 0.f; }
    }

    for (int it = 0; it < 8; it++) {
        const int s = it & 3;
        if (it + 2 < 8) loadC(it + 2, (it + 2) & 3);
        else cp_commit();
        cp_wait<2>();
        __syncthreads();

        float sacc[2][4][4];
#pragma unroll
        for (int i = 0; i < 2; i++)
#pragma unroll
            for (int j = 0; j < 4; j++)
#pragma unroll
                for (int r = 0; r < 4; r++) sacc[i][j][r] = 0.f;

#pragma unroll
        for (int zc = 0; zc < 2; zc++) {
            uint4 a[2][2];
#pragma unroll
            for (int mt = 0; mt < 2; mt++) {
                int mr = wq * 32 + mt * 16 + group;
                a[mt][0] = *reinterpret_cast<const uint4*>(&Rt[zc][mr][tg * 8]);
                a[mt][1] = *reinterpret_cast<const uint4*>(&Rt[zc][mr + 8][tg * 8]);
            }
#pragma unroll
            for (int nt = 0; nt < 4; nt++) {
                int nc = wk * 32 + nt * 8 + group;
                uint4 bb = *reinterpret_cast<const uint4*>(&Ct[s][zc][nc][tg * 8]);
#pragma unroll
                for (int mt = 0; mt < 2; mt++) {
                    mma_f16(sacc[mt][nt], a[mt][0].x, a[mt][1].x, a[mt][0].y, a[mt][1].y,
                            bb.x, bb.y);
                    mma_f16(sacc[mt][nt], a[mt][0].z, a[mt][1].z, a[mt][0].w, a[mt][1].w,
                            bb.z, bb.w);
                }
            }
        }

        const int pcur = it & 1;
        const int pprev = pcur ^ 1;
        const int sprev = (it + 3) & 3;

#pragma unroll
        for (int j = 0; j < 4; j++) {
            if (it > 0) {
                uint4 a[2][2];
#pragma unroll
                for (int mt = 0; mt < 2; mt++) {
                    int mr = wq * 32 + mt * 16 + group;
                    a[mt][0] = *reinterpret_cast<const uint4*>(&P[pprev][j][mr][tg * 8]);
                    a[mt][1] = *reinterpret_cast<const uint4*>(&P[pprev][j][mr + 8][tg * 8]);
                }
#pragma unroll
                for (int nt = 0; nt < 2; nt++) {
                    int nc = wk * 16 + nt * 8 + group;
                    uint4 bb = *reinterpret_cast<const uint4*>(&T2[sprev][j][nc][tg * 8]);
#pragma unroll
                    for (int mt = 0; mt < 2; mt++) {
                        mma_f16(av[mt][nt], a[mt][0].x, a[mt][1].x, a[mt][0].y, a[mt][1].y,
                                bb.x, bb.y);
                        mma_f16(av[mt][nt], a[mt][0].z, a[mt][1].z, a[mt][0].w, a[mt][1].w,
                                bb.z, bb.w);
                    }
                }
            }
#pragma unroll
            for (int mt = 0; mt < 2; mt++) {
                int r0 = wq * 32 + mt * 16 + group;
                float v0 = __expf(beta * sacc[mt][j][0]);
                float v1 = __expf(beta * sacc[mt][j][1]);
                float v2 = __expf(beta * sacc[mt][j][2]);
                float v3 = __expf(beta * sacc[mt][j][3]);
                if (DO_ZINV) { rs[mt][0] += v0 + v1; rs[mt][1] += v2 + v3; }
                int colw = j * 8 + tg * 2;
                *reinterpret_cast<__half2*>(&P[pcur][wk][r0][colw]) =
                    __floats2half2_rn(v0, v1);
                *reinterpret_cast<__half2*>(&P[pcur][wk][r0 + 8][colw]) =
                    __floats2half2_rn(v2, v3);
            }
        }
        __syncthreads();
    }

#pragma unroll
    for (int j = 0; j < 4; j++) {
        uint4 a[2][2];
#pragma unroll
        for (int mt = 0; mt < 2; mt++) {
            int mr = wq * 32 + mt * 16 + group;
            a[mt][0] = *reinterpret_cast<const uint4*>(&P[1][j][mr][tg * 8]);
            a[mt][1] = *reinterpret_cast<const uint4*>(&P[1][j][mr + 8][tg * 8]);
        }
#pragma unroll
        for (int nt = 0; nt < 2; nt++) {
            int nc = wk * 16 + nt * 8 + group;
            uint4 bb = *reinterpret_cast<const uint4*>(&T2[3][j][nc][tg * 8]);
#pragma unroll
            for (int mt = 0; mt < 2; mt++) {
                mma_f16(av[mt][nt], a[mt][0].x, a[mt][1].x, a[mt][0].y, a[mt][1].y,
                        bb.x, bb.y);
                mma_f16(av[mt][nt], a[mt][0].z, a[mt][1].z, a[mt][0].w, a[mt][1].w,
                        bb.z, bb.w);
            }
        }
    }

    if (DO_ZINV) {
#pragma unroll
        for (int mt = 0; mt < 2; mt++) {
#pragma unroll
            for (int h = 0; h < 2; h++) {
                float v = rs[mt][h];
                v += __shfl_xor_sync(0xffffffffu, v, 1);
                v += __shfl_xor_sync(0xffffffffu, v, 2);
                if (tg == 0)
                    red[wk][wq * 32 + mt * 16 + h * 8 + group] = v;
            }
        }
        __syncthreads();
        if (tid < 64) {
            float ssum = red[0][tid] + red[1][tid] + red[2][tid] + red[3][tid];
            float zi = 1.f / ssum;
            zs[tid] = zi;
            zinvg[(long)bh * Nc + blk * 64 + tid] = zi;
        }
        __syncthreads();
    }

#pragma unroll
    for (int mt = 0; mt < 2; mt++) {
#pragma unroll
        for (int nt = 0; nt < 2; nt++) {
            int col = wk * 16 + nt * 8 + tg * 2;
#pragma unroll
            for (int h = 0; h < 2; h++) {
                int row = wq * 32 + mt * 16 + h * 8 + group;
                float v0 = av[mt][nt][h * 2 + 0];
                float v1 = av[mt][nt][h * 2 + 1];
                if (DO_ZINV) {
                    float zi = zs[row];
                    v0 *= zi; v1 *= zi;
                }
                *reinterpret_cast<__half2*>(&Outb[(long)row * ldo + col]) =
                    __floats2half2_rn(v0, v1);
            }
        }
    }
}

// ===========================================================================
// Dense half GEMM, BK=64: C = A[m][k] @ B[n][k]^T.
// smem is [NST][2 chunk][rows][32] per operand — each chunk keeps the proven
// conflict-free BK=32 geometry for both cp.async stores and LDS.128 loads.
// E_PROJ: gn < 1536 -> QK (ld D2); gn >= 1536 -> relu -> C2 (ld KC).
// ===========================================================================
template <int BM, int BN, int WM, int WN, int EPI>
__global__ __launch_bounds__((BM / WM) * (BN / WN) * 32)
void gemm_h(const __half* __restrict__ A, const __half* __restrict__ Bm,
            void* __restrict__ Cbase, void* __restrict__ C2base,
            int K, int lda, int ldb, int ldc)
{
    constexpr int BK = 64;
    constexpr int NW = (BM / WM) * (BN / WN);
    constexpr int NT = NW * 32;
    constexpr int MT = WM / 16;
    constexpr int NTI = WN / 8;
    constexpr int NST = 3;

    extern __shared__ __align__(16) __half dsm[];
    // As: [NST][2][BM][32], Bs: [NST][2][BN][32]
    __half (*As)[2][BM][32] = reinterpret_cast<__half(*)[2][BM][32]>(dsm);
    __half (*Bs)[2][BN][32] =
        reinterpret_cast<__half(*)[2][BN][32]>(dsm + (size_t)NST * 2 * BM * 32);

    const int t = threadIdx.x;
    const int warp = t >> 5;
    const int lane = t & 31;
    const int group = lane >> 2;
    const int tg = lane & 3;
    const int wm = warp / (BN / WN);
    const int wn = warp % (BN / WN);
    const int m0 = blockIdx.y * BM;
    const int n0 = blockIdx.x * BN;

    const int nk = K / BK;

    auto prefetch = [&](int kt, int s) {
        const int k0 = kt * BK;
#pragma unroll
        for (int ch = 0; ch < 2; ch++) {
#pragma unroll
            for (int it = 0; it < (BM * 4) / NT; ++it) {
                int c = t + it * NT;
                int m = c >> 2, q = c & 3;
                cp_async16(&As[s][ch][m][q * 8],
                           &A[(long)(m0 + m) * lda + k0 + ch * 32 + q * 8]);
            }
#pragma unroll
            for (int it = 0; it < (BN * 4) / NT; ++it) {
                int c = t + it * NT;
                int n = c >> 2, q = c & 3;
                cp_async16(&Bs[s][ch][n][q * 8],
                           &Bm[(long)(n0 + n) * ldb + k0 + ch * 32 + q * 8]);
            }
        }
        cp_commit();
    };

    float acc[MT][NTI][4];
#pragma unroll
    for (int i = 0; i < MT; i++)
#pragma unroll
        for (int j = 0; j < NTI; j++)
#pragma unroll
            for (int r = 0; r < 4; r++) acc[i][j][r] = 0.f;

    prefetch(0, 0);
    if (nk > 1) prefetch(1, 1); else cp_commit();

    for (int kt = 0; kt < nk; kt++) {
        const int s = kt % NST;
        if (kt + 2 < nk) prefetch(kt + 2, (kt + 2) % NST);
        else cp_commit();
        cp_wait<2>();
        __syncthreads();

#pragma unroll
        for (int ch = 0; ch < 2; ch++) {
            uint4 a4[MT][2];
            uint4 b4[NTI];
#pragma unroll
            for (int mt = 0; mt < MT; mt++) {
                int mr = wm * WM + mt * 16 + group;
                a4[mt][0] = *reinterpret_cast<const uint4*>(&As[s][ch][mr][tg * 8]);
                a4[mt][1] = *reinterpret_cast<const uint4*>(&As[s][ch][mr + 8][tg * 8]);
            }
#pragma unroll
            for (int nt = 0; nt < NTI; nt++) {
                int nc = wn * WN + nt * 8 + group;
                b4[nt] = *reinterpret_cast<const uint4*>(&Bs[s][ch][nc][tg * 8]);
            }
#pragma unroll
            for (int mt = 0; mt < MT; mt++)
#pragma unroll
                for (int nt = 0; nt < NTI; nt++)
                    mma_f16(acc[mt][nt], a4[mt][0].x, a4[mt][1].x, a4[mt][0].y, a4[mt][1].y,
                            b4[nt].x, b4[nt].y);
#pragma unroll
            for (int mt = 0; mt < MT; mt++)
#pragma unroll
                for (int nt = 0; nt < NTI; nt++)
                    mma_f16(acc[mt][nt], a4[mt][0].z, a4[mt][1].z, a4[mt][0].w, a4[mt][1].w,
                            b4[nt].z, b4[nt].w);
        }
        __syncthreads();
    }

#pragma unroll
    for (int mt = 0; mt < MT; mt++) {
#pragma unroll
        for (int nt = 0; nt < NTI; nt++) {
            int gm = m0 + wm * WM + mt * 16 + group;
            int gn = n0 + wn * WN + nt * 8 + tg * 2;
#pragma unroll
            for (int half = 0; half < 2; half++) {
                int row = gm + half * 8;
                float v0 = acc[mt][nt][half * 2 + 0];
                float v1 = acc[mt][nt][half * 2 + 1];
                if (EPI == E_PROJ) {
                    if (gn < D2) {
                        __half* C = (__half*)Cbase;
                        *reinterpret_cast<__half2*>(&C[(long)row * D2 + gn]) =
                            __floats2half2_rn(v0, v1);
                    } else {
                        v0 = fmaxf(v0, 0.f); v1 = fmaxf(v1, 0.f);
                        __half* C2 = (__half*)C2base;
                        *reinterpret_cast<__half2*>(&C2[(long)row * KC + gn]) =
                            __floats2half2_rn(v0, v1);
                    }
                } else {
                    float* C = (float*)Cbase;
                    float2 w; w.x = v0; w.y = v1;
                    *reinterpret_cast<float2*>(&C[(long)row * ldc + gn]) = w;
                }
            }
        }
    }
}

// ===========================================================================
// Pre-pass kernels
// ===========================================================================
__global__ __launch_bounds__(256) void hconv_k(const float* __restrict__ src,
                                               __half* __restrict__ dst, long n4)
{
    long i = (long)blockIdx.x * 256 + threadIdx.x;
    if (i >= n4) return;
    float4 v = reinterpret_cast<const float4*>(src)[i];
    __half2 h0 = __floats2half2_rn(v.x, v.y);
    __half2 h1 = __floats2half2_rn(v.z, v.w);
    uint2 u;
    u.x = *reinterpret_cast<uint32_t*>(&h0);
    u.y = *reinterpret_cast<uint32_t*>(&h1);
    reinterpret_cast<uint2*>(dst)[i] = u;
}

__global__ __launch_bounds__(256) void htrans_k(const float* __restrict__ src,
                                                __half* __restrict__ dst,
                                                int R, int C, int dld)
{
    __shared__ float tile[32][33];
    int c0 = blockIdx.x * 32, r0 = blockIdx.y * 32;
    int tx = threadIdx.x & 31, ty = threadIdx.x >> 5;
    for (int i = ty; i < 32; i += 8)
        tile[i][tx] = src[(long)(r0 + i) * C + c0 + tx];
    __syncthreads();
    for (int i = ty; i < 32; i += 8)
        dst[(long)(c0 + i) * dld + r0 + tx] = __float2half(tile[tx][i]);
}

__global__ __launch_bounds__(256) void ktrans_h(const __half* __restrict__ src0,
                                                int ldk, __half* __restrict__ KT)
{
    __shared__ __half tile[32][33];
    int s0 = blockIdx.x * 32, z0 = blockIdx.y * 32, bh = blockIdx.z;
    int b = bh / Hc, h = bh % Hc;
    int tx = threadIdx.x & 31, ty = threadIdx.x >> 5;
    const __half* src = src0 + (long)b * Nc * ldk + h * Zc;
    for (int i = ty; i < 32; i += 8)
        tile[i][tx] = src[(long)(s0 + i) * ldk + z0 + tx];
    __syncthreads();
    __half* dst = KT + (long)bh * Zc * Nc;
    for (int i = ty; i < 32; i += 8)
        dst[(long)(z0 + i) * Nc + s0 + tx] = tile[tx][i];
}

__global__ __launch_bounds__(256) void qstrans_h(const __half* __restrict__ src0,
                                                 int ldq,
                                                 const float* __restrict__ zinv,
                                                 __half* __restrict__ QT)
{
    __shared__ __half tile[32][33];
    int s0 = blockIdx.x * 32, z0 = blockIdx.y * 32, bh = blockIdx.z;
    int b = bh / Hc, h = bh % Hc;
    int tx = threadIdx.x & 31, ty = threadIdx.x >> 5;
    const __half* src = src0 + (long)b * Nc * ldq + h * Zc;
    const float* zv = zinv + (long)bh * Nc;
    for (int i = ty; i < 32; i += 8) {
        float v = __half2float(src[(long)(s0 + i) * ldq + z0 + tx]) * zv[s0 + i];
        tile[i][tx] = __float2half(v);
    }
    __syncthreads();
    __half* dst = QT + (long)bh * Zc * Nc;
    for (int i = ty; i < 32; i += 8)
        dst[(long)(z0 + i) * Nc + s0 + tx] = tile[tx][i];
}

// ===========================================================================
template <int BM, int BN, int WM, int WN, int EPI>
static void run_h(const __half* A, const __half* B, void* C, void* C2,
                  int M, int N, int K, int lda, int ldb, int ldc)
{
    constexpr int SM = 3 * 2 * (BM + BN) * 32 * 2;   // NST*2chunks*(rows)*32 halfs
    cudaFuncSetAttribute(gemm_h<BM, BN, WM, WN, EPI>,
                         cudaFuncAttributeMaxDynamicSharedMemorySize, SM);
    dim3 grid(N / BN, M / BM);
    gemm_h<BM, BN, WM, WN, EPI>
        <<<grid, (BM / WM) * (BN / WN) * 32, SM>>>(A, B, C, C2, K, lda, ldb, ldc);
}

extern "C" void kernel_launch(void* const* d_in, const int* in_sizes, int n_in,
                              void* d_out, int out_size)
{
    const float* x     = (const float*)d_in[0];
    const float* Wq    = (const float*)d_in[1];
    const float* Wk    = (const float*)d_in[2];
    const float* betas = (const float*)d_in[3];
    const float* Wmlp  = (const float*)d_in[4];
    float* out = (float*)d_out;

    __half *QKh, *KTh, *QsTh, *AVh, *xh, *WcatH, *WallTh;
    float *Zinv;
    cudaGetSymbolAddress((void**)&QKh,    g_QKh);
    cudaGetSymbolAddress((void**)&KTh,    g_KTh);
    cudaGetSymbolAddress((void**)&QsTh,   g_QsTh);
    cudaGetSymbolAddress((void**)&AVh,    g_AVh);
    cudaGetSymbolAddress((void**)&Zinv,   g_Zinv);
    cudaGetSymbolAddress((void**)&xh,     g_xh);
    cudaGetSymbolAddress((void**)&WcatH,  g_WcatH);
    cudaGetSymbolAddress((void**)&WallTh, g_WallTh);

    cudaFuncSetAttribute(fa_k<1>, cudaFuncAttributeMaxDynamicSharedMemorySize, fa::SMEM);
    cudaFuncSetAttribute(fa_k<0>, cudaFuncAttributeMaxDynamicSharedMemorySize, fa::SMEM);

    // ---- half conversions: x, stacked weight rows [Wq;Wk;Wmlp] ----
    hconv_k<<<(Mrows * Dc / 4 + 255) / 256, 256>>>(x, xh, Mrows * Dc / 4);
    hconv_k<<<(Dc * Dc / 4 + 255) / 256, 256>>>(Wq, WcatH, Dc * Dc / 4);
    hconv_k<<<(Dc * Dc / 4 + 255) / 256, 256>>>(Wk, WcatH + (size_t)Dc * Dc, Dc * Dc / 4);
    hconv_k<<<(HIDc * Dc / 4 + 255) / 256, 256>>>(Wmlp, WcatH + (size_t)D2 * Dc,
                                                  HIDc * Dc / 4);
    htrans_k<<<dim3(Dc / 32, Dc / 32), 256>>>(Wq, WallTh, Dc, Dc, KC);
    htrans_k<<<dim3(Dc / 32, Dc / 32), 256>>>(Wk, WallTh + Dc, Dc, Dc, KC);
    htrans_k<<<dim3(Dc / 32, HIDc / 32), 256>>>(Wmlp, WallTh + D2, HIDc, Dc, KC);

    // 1) [Q|K|hid] = x @ Wcat^T  (one GEMM; hid -> AVh cols 1536:4608, relu)
    run_h<128, 128, 64, 64, E_PROJ>(xh, WcatH, QKh, AVh,
                                    Mrows, KC, Dc, Dc, Dc, 0);

    // KT for FA1's T2 operand (K = QKh cols 768:1536)
    ktrans_h<<<dim3(Nc / 32, Zc / 32, Bc * Hc), 256>>>(QKh + Dc, D2, KTh);

    // 2) FA1: AV1 -> AVh[:,0:768], Zinv inline  (R=Q, C=K, T2=KT)
    fa_k<1><<<dim3(Nc / 64, Bc * Hc), 256, fa::SMEM>>>(
        QKh, D2, QKh + Dc, D2, KTh, AVh, KC, Zinv, betas);

    // 3) QsT = diag(Zinv) Q transposed; FA2: AV2 -> AVh[:,768:1536]
    qstrans_h<<<dim3(Nc / 32, Zc / 32, Bc * Hc), 256>>>(QKh, D2, Zinv, QsTh);
    fa_k<0><<<dim3(Nc / 64, Bc * Hc), 256, fa::SMEM>>>(
        QKh + Dc, D2, QKh, D2, QsTh, AVh + Dc, KC, Zinv, betas);

    // 4) out = [AV1|AV2|hid] @ Wall  (single K=4608 GEMM, fp32 out)
    run_h<128, 128, 64, 64, E_STOREF>(AVh, WallTh, out, nullptr,
                                      Mrows, Dc, KC, KC, KC, Dc);
}